// round 13
// baseline (speedup 1.0000x reference)
#include <cuda_runtime.h>
#include <cuda_bf16.h>
#include <math.h>
#include <stdint.h>

#define NN 50000
#define EE 800000
#define CC 64
#define HH 192
#define H3 576
#define EDIM 16
#define GG 2048
#define H0ROWS 25088  // 128-aligned node split for gather/GRU pipelining

// ---------------- scratch ----------------
__device__ __align__(16) float g_x[NN * HH];
__device__ __align__(16) float g_hW[NN * HH];
__device__ __align__(16) float g_gh[NN * H3];
__device__ float g_s[NN];
__device__ float g_d[NN];
__device__ float g_ae[EE];
__device__ float g_ew[EE];
__device__ float g_v[EDIM];
__device__ float g_loopsum[1];
__device__ __align__(16) float g_out[GG * HH];
__device__ float g_smol[NN];
__device__ float g_dmol[GG];
__device__ float g_bp_ih[H3];
__device__ float g_bp_hh[H3];
__device__ float g_bp_mi[H3];
__device__ float g_bp_mh[H3];
// CSR
__device__ int g_deg[NN];
__device__ int g_cursor[NN];
__device__ int g_rowptr[NN + 1];
__device__ int g_eid[EE];
__device__ int g_esrc[EE];
__device__ int g_bsums[64];
__device__ int g_molptr[GG + 1];
// bf16x3 split buffers
__device__ __align__(16) __nv_bfloat16 g_a3[(size_t)NN * H3];
__device__ __align__(16) __nv_bfloat16 g_a3b[(size_t)NN * H3];
__device__ __align__(16) __nv_bfloat16 g_b3[(size_t)H3 * H3];
__device__ __align__(16) __nv_bfloat16 g_b3wd[(size_t)H3 * H3];
__device__ __align__(16) __nv_bfloat16 g_b3wi[(size_t)H3 * H3];
__device__ __align__(16) __nv_bfloat16 g_b3wh[(size_t)H3 * H3];
__device__ __align__(16) __nv_bfloat16 g_a3m[(size_t)GG * H3];
__device__ __align__(16) __nv_bfloat16 g_a3m2[(size_t)GG * H3];

// ---------------- helpers ----------------
__device__ __forceinline__ float warp_sum(float v) {
#pragma unroll
    for (int o = 16; o; o >>= 1) v += __shfl_down_sync(0xffffffffu, v, o);
    return v;
}
__device__ __forceinline__ float sigm(float x) { return 1.f / (1.f + expf(-x)); }
__device__ __forceinline__ uint32_t smem_u32(const void* p) {
    uint32_t a;
    asm("{ .reg .u64 t; cvta.to.shared.u64 t, %1; cvt.u32.u64 %0, t; }" : "=r"(a) : "l"(p));
    return a;
}
__device__ __forceinline__ void cp16(uint32_t s, const void* g) {
    asm volatile("cp.async.cg.shared.global [%0], [%1], 16;" :: "r"(s), "l"(g));
}
__device__ __forceinline__ void ldsm4(uint32_t& r0, uint32_t& r1, uint32_t& r2, uint32_t& r3,
                                      uint32_t addr) {
    asm volatile("ldmatrix.sync.aligned.m8n8.x4.shared.b16 {%0,%1,%2,%3}, [%4];"
                 : "=r"(r0), "=r"(r1), "=r"(r2), "=r"(r3) : "r"(addr));
}
__device__ __forceinline__ void mma16816(float* d, const uint32_t* a, const uint32_t* b) {
    asm volatile(
        "mma.sync.aligned.m16n8k16.row.col.f32.bf16.bf16.f32 "
        "{%0,%1,%2,%3}, {%4,%5,%6,%7}, {%8,%9}, {%0,%1,%2,%3};"
        : "+f"(d[0]), "+f"(d[1]), "+f"(d[2]), "+f"(d[3])
        : "r"(a[0]), "r"(a[1]), "r"(a[2]), "r"(a[3]), "r"(b[0]), "r"(b[1]));
}
__device__ __forceinline__ void redf(float* p, float v) {
    asm volatile("red.global.add.f32 [%0], %1;" :: "l"(p), "f"(v) : "memory");
}
__device__ __forceinline__ unsigned short bfb(__nv_bfloat16 h) {
    return *reinterpret_cast<unsigned short*>(&h);
}
__device__ __forceinline__ void store_split4(__nv_bfloat16* base, float v0, float v1,
                                             float v2, float v3) {
    __nv_bfloat16 h0 = __float2bfloat16_rn(v0), h1 = __float2bfloat16_rn(v1);
    __nv_bfloat16 h2 = __float2bfloat16_rn(v2), h3 = __float2bfloat16_rn(v3);
    __nv_bfloat16 l0 = __float2bfloat16_rn(v0 - __bfloat162float(h0));
    __nv_bfloat16 l1 = __float2bfloat16_rn(v1 - __bfloat162float(h1));
    __nv_bfloat16 l2 = __float2bfloat16_rn(v2 - __bfloat162float(h2));
    __nv_bfloat16 l3 = __float2bfloat16_rn(v3 - __bfloat162float(h3));
    uint2 hp, lp;
    hp.x = ((uint32_t)bfb(h1) << 16) | bfb(h0);
    hp.y = ((uint32_t)bfb(h3) << 16) | bfb(h2);
    lp.x = ((uint32_t)bfb(l1) << 16) | bfb(l0);
    lp.y = ((uint32_t)bfb(l3) << 16) | bfb(l2);
    *(uint2*)(base) = hp;
    *(uint2*)(base + HH) = hp;
    *(uint2*)(base + 2 * HH) = lp;
}

// ===== bf16 mma.sync NT GEMM: 128x96 tile, 256 threads, 2 CTAs/SM, 3-stage pipeline =====
#define BN 96
#define A_BUF 16384
#define B_BUF 12288
#define BG_SMEM (3 * A_BUF + 3 * B_BUF)
template <int EPI, bool SPLIT, bool DOT, bool GRUF>
__global__ void __launch_bounds__(256, 2)
bgemm(const __nv_bfloat16* __restrict__ A3, const __nv_bfloat16* __restrict__ B3,
      const float* __restrict__ bias, float* __restrict__ C,
      __nv_bfloat16* __restrict__ C3,
      const float* __restrict__ u, const float* __restrict__ w,
      float* __restrict__ ou, float* __restrict__ ow,
      const float* __restrict__ gh, float* __restrict__ xb,
      int M, int Nc, int K3, int row_base) {
    extern __shared__ __align__(16) char dsm[];
    const int tid = threadIdx.x;
    const int lane = tid & 31, wid = tid >> 5;
    const int wm = wid & 3, wn = wid >> 2;
    const int row0 = row_base + blockIdx.y * 128, col0 = blockIdx.x * BN;
    const uint32_t aB = smem_u32(dsm);
    const uint32_t bB = aB + 3 * A_BUF;

    float acc[2][6][4] = {};
    const int nc = K3 >> 6;

    auto issue = [&](int c, int buf) {
        const uint32_t ab = aB + buf * A_BUF;
        const uint32_t bb = bB + buf * B_BUF;
#pragma unroll
        for (int q = 0; q < 4; q++) {
            int idx = q * 256 + tid;
            int r = idx >> 3, kc = idx & 7;
            int grow = row0 + r;
            grow = grow < M ? grow : M - 1;
            cp16(ab + (uint32_t)(r * 128 + ((kc * 16) ^ ((r & 7) << 4))),
                 A3 + (size_t)grow * K3 + c * 64 + kc * 8);
        }
#pragma unroll
        for (int q = 0; q < 3; q++) {
            int idx = q * 256 + tid;
            int r = idx >> 3, kc = idx & 7;
            cp16(bb + (uint32_t)(r * 128 + ((kc * 16) ^ ((r & 7) << 4))),
                 B3 + (size_t)(col0 + r) * K3 + c * 64 + kc * 8);
        }
        asm volatile("cp.async.commit_group;" ::: "memory");
    };

    const int a_r = wm * 32 + ((lane >> 3) & 1) * 8 + (lane & 7);
    const int a_kb = ((lane >> 4) & 1) * 16;
    const int b_r = wn * 48 + ((lane >> 4) & 1) * 8 + (lane & 7);
    const int b_kb = ((lane >> 3) & 1) * 16;

    issue(0, 0);
    issue(1, 1);
    for (int c = 0; c < nc; c++) {
        const int buf = c % 3;
        if (c + 2 < nc) {
            issue(c + 2, (c + 2) % 3);
            asm volatile("cp.async.wait_group 2;" ::: "memory");
        } else if (c + 1 < nc) {
            asm volatile("cp.async.wait_group 1;" ::: "memory");
        } else {
            asm volatile("cp.async.wait_group 0;" ::: "memory");
        }
        __syncthreads();
        const uint32_t ab = aB + buf * A_BUF;
        const uint32_t bb = bB + buf * B_BUF;
#pragma unroll
        for (int ks = 0; ks < 4; ks++) {
            uint32_t af[2][4], bfr[3][4];
#pragma unroll
            for (int mi = 0; mi < 2; mi++) {
                int r = a_r + mi * 16;
                ldsm4(af[mi][0], af[mi][1], af[mi][2], af[mi][3],
                      ab + (uint32_t)(r * 128 + ((ks * 32 + a_kb) ^ ((r & 7) << 4))));
            }
#pragma unroll
            for (int p = 0; p < 3; p++) {
                int r = b_r + p * 16;
                ldsm4(bfr[p][0], bfr[p][1], bfr[p][2], bfr[p][3],
                      bb + (uint32_t)(r * 128 + ((ks * 32 + b_kb) ^ ((r & 7) << 4))));
            }
#pragma unroll
            for (int mi = 0; mi < 2; mi++)
#pragma unroll
                for (int ni = 0; ni < 6; ni++) {
                    uint32_t b2[2] = {bfr[ni >> 1][(ni & 1) * 2], bfr[ni >> 1][(ni & 1) * 2 + 1]};
                    mma16816(acc[mi][ni], af[mi], b2);
                }
        }
        __syncthreads();
    }

    const int qr = lane >> 2, qc = (lane & 3) * 2;

    if (GRUF) {
        float* S = (float*)dsm;
        const int ST = 100;
        const int r_l = tid >> 3;
        const int f0 = (tid & 7) * 4;
#pragma unroll
        for (int mi = 0; mi < 2; mi++) {
#pragma unroll
            for (int half = 0; half < 2; half++) {
#pragma unroll
                for (int ni = 0; ni < 6; ni++) {
                    int cl = wn * 48 + ni * 8 + qc;
                    float v0 = acc[mi][ni][half * 2 + 0] + bias[col0 + cl];
                    float v1 = acc[mi][ni][half * 2 + 1] + bias[col0 + cl + 1];
                    *(float2*)&S[(wm * 8 + qr) * ST + cl] = make_float2(v0, v1);
                }
                __syncthreads();
                int row = row0 + (r_l >> 3) * 32 + mi * 16 + half * 8 + (r_l & 7);
                if (row < M) {
                    const float* Sr = &S[r_l * ST + 3 * f0];
                    const float* ghr = gh + (size_t)row * Nc + col0 + 3 * f0;
                    int fg = col0 / 3 + f0;
                    float4 xv = *(const float4*)(xb + (size_t)row * HH + fg);
                    float xo[4] = {xv.x, xv.y, xv.z, xv.w};
                    float o[4];
#pragma unroll
                    for (int q = 0; q < 4; q++) {
                        float gir = Sr[3 * q], giz = Sr[3 * q + 1], gin = Sr[3 * q + 2];
                        float hr = ghr[3 * q], hz = ghr[3 * q + 1], hn = ghr[3 * q + 2];
                        float r = sigm(gir + hr);
                        float z = sigm(giz + hz);
                        float n = tanhf(gin + r * hn);
                        float v = (1.f - z) * n + z * xo[q];
                        o[q] = v > 0.f ? v : 0.f;
                    }
                    *(float4*)(xb + (size_t)row * HH + fg) = make_float4(o[0], o[1], o[2], o[3]);
                    store_split4(C3 + (size_t)row * H3 + fg, o[0], o[1], o[2], o[3]);
                }
                __syncthreads();
            }
        }
        return;
    }

#pragma unroll
    for (int mi = 0; mi < 2; mi++) {
#pragma unroll
        for (int half = 0; half < 2; half++) {
            int row = row0 + wm * 32 + mi * 16 + half * 8 + qr;
            bool ok = row < M;
            float p_s = 0.f, p_d = 0.f;
#pragma unroll
            for (int ni = 0; ni < 6; ni++) {
                int cc0 = col0 + wn * 48 + ni * 8 + qc;
                float v0 = acc[mi][ni][half * 2 + 0];
                float v1 = acc[mi][ni][half * 2 + 1];
                if (EPI >= 1) { v0 += bias[cc0]; v1 += bias[cc0 + 1]; }
                if (EPI == 2) {
                    v0 = v0 > 0.f ? v0 : 0.01f * v0;
                    v1 = v1 > 0.f ? v1 : 0.01f * v1;
                }
                if (DOT) {
                    p_s += v0 * u[cc0] + v1 * u[cc0 + 1];
                    if (w) p_d += v0 * w[cc0] + v1 * w[cc0 + 1];
                }
                if (ok && C) *(float2*)(C + (size_t)row * Nc + cc0) = make_float2(v0, v1);
                if (SPLIT && ok) {
                    size_t base = (size_t)row * (3 * Nc) + cc0;
                    __nv_bfloat16 h0 = __float2bfloat16_rn(v0);
                    __nv_bfloat16 l0 = __float2bfloat16_rn(v0 - __bfloat162float(h0));
                    __nv_bfloat16 h1 = __float2bfloat16_rn(v1);
                    __nv_bfloat16 l1 = __float2bfloat16_rn(v1 - __bfloat162float(h1));
                    C3[base] = h0; C3[base + 1] = h1;
                    C3[base + Nc] = h0; C3[base + Nc + 1] = h1;
                    C3[base + 2 * Nc] = l0; C3[base + 2 * Nc + 1] = l1;
                }
            }
            if (DOT) {
                p_s += __shfl_xor_sync(0xffffffffu, p_s, 1);
                p_s += __shfl_xor_sync(0xffffffffu, p_s, 2);
                if (w) {
                    p_d += __shfl_xor_sync(0xffffffffu, p_d, 1);
                    p_d += __shfl_xor_sync(0xffffffffu, p_d, 2);
                }
                if (ok && (lane & 3) == 0) {
                    redf(ou + row, p_s);
                    if (w) redf(ow + row, p_d);
                }
            }
        }
    }
}

// ---------------- split kernels ----------------
__global__ void k_splitA(const float* __restrict__ X, __nv_bfloat16* __restrict__ Y) {
    int idx = blockIdx.x * 256 + threadIdx.x;
    if (idx < NN) { g_s[idx] = 0.f; g_d[idx] = 0.f; }
    if (idx >= NN * CC) return;
    int r = idx / CC, j = idx % CC;
    float v = X[idx];
    __nv_bfloat16 hi = __float2bfloat16_rn(v);
    __nv_bfloat16 lo = __float2bfloat16_rn(v - __bfloat162float(hi));
    size_t b = (size_t)r * 3 * CC + j;
    Y[b] = hi; Y[b + CC] = hi; Y[b + 2 * CC] = lo;
}
__global__ void k_splitB(const float* __restrict__ X, __nv_bfloat16* __restrict__ Y,
                         int rows, int K) {
    int idx = blockIdx.x * 256 + threadIdx.x;
    if (idx >= rows * K) return;
    int r = idx / K, j = idx % K;
    float v = X[idx];
    __nv_bfloat16 hi = __float2bfloat16_rn(v);
    __nv_bfloat16 lo = __float2bfloat16_rn(v - __bfloat162float(hi));
    size_t b = (size_t)r * 3 * K + j;
    Y[b] = hi; Y[b + K] = lo; Y[b + 2 * K] = hi;
}
__global__ void k_splitB2(const float* __restrict__ X1, __nv_bfloat16* __restrict__ Y1,
                          const float* __restrict__ X2, __nv_bfloat16* __restrict__ Y2) {
    int idx = blockIdx.x * 256 + threadIdx.x;
    const int n1 = HH * CC;
    if (idx < n1) {
        int r = idx / CC, j = idx % CC;
        float v = X1[idx];
        __nv_bfloat16 hi = __float2bfloat16_rn(v);
        __nv_bfloat16 lo = __float2bfloat16_rn(v - __bfloat162float(hi));
        size_t b = (size_t)r * 3 * CC + j;
        Y1[b] = hi; Y1[b + CC] = lo; Y1[b + 2 * CC] = hi;
    }
    int i2 = idx - n1;
    if (i2 >= 0 && i2 < HH * HH) {
        int r = i2 / HH, j = i2 % HH;
        float v = X2[i2];
        __nv_bfloat16 hi = __float2bfloat16_rn(v);
        __nv_bfloat16 lo = __float2bfloat16_rn(v - __bfloat162float(hi));
        size_t b = (size_t)r * 3 * HH + j;
        Y2[b] = hi; Y2[b + HH] = lo; Y2[b + 2 * HH] = hi;
    }
}
__global__ void k_splitB_perm(const float* __restrict__ X, __nv_bfloat16* __restrict__ Y) {
    int idx = blockIdx.x * 256 + threadIdx.x;
    if (idx >= H3 * HH) return;
    int j = idx / HH, k = idx % HH;
    int g = j / HH, f = j % HH;
    int rp = 3 * f + g;
    float v = X[idx];
    __nv_bfloat16 hi = __float2bfloat16_rn(v);
    __nv_bfloat16 lo = __float2bfloat16_rn(v - __bfloat162float(hi));
    size_t b = (size_t)rp * H3 + k;
    Y[b] = hi; Y[b + HH] = lo; Y[b + 2 * HH] = hi;
}
__global__ void k_permbias(const float* __restrict__ b1, float* __restrict__ o1,
                           const float* __restrict__ b2, float* __restrict__ o2) {
    int j = threadIdx.x;
    int g = j / HH, f = j % HH;
    o1[3 * f + g] = b1[j];
    o2[3 * f + g] = b2[j];
}

// ---------------- CSR build ----------------
__global__ void k_zero_int(int* p, int n) {
    int i = blockIdx.x * 256 + threadIdx.x;
    if (i < n) p[i] = 0;
}
__global__ void k_zero2(float* a, float* b, int na, int nb) {
    int i = blockIdx.x * 256 + threadIdx.x;
    if (i < na) a[i] = 0.f;
    if (i < nb) b[i] = 0.f;
}
__global__ void k_hist(const int* __restrict__ dst) {
    int e = blockIdx.x * 256 + threadIdx.x;
    if (e < EE) atomicAdd(&g_deg[dst[e]], 1);
}
#define SCAN_BLK 1024
#define NSCAN 49
__global__ void k_scan_block() {
    __shared__ int s[SCAN_BLK];
    int b = blockIdx.x, t = threadIdx.x;
    int i = b * SCAN_BLK + t;
    int v = (i < NN) ? g_deg[i] : 0;
    s[t] = v;
    __syncthreads();
    for (int off = 1; off < SCAN_BLK; off <<= 1) {
        int x = (t >= off) ? s[t - off] : 0;
        __syncthreads();
        s[t] += x;
        __syncthreads();
    }
    if (i < NN) g_rowptr[i] = s[t] - v;
    if (t == SCAN_BLK - 1) g_bsums[b] = s[t];
}
__global__ void k_scan_mid() {
    if (threadIdx.x == 0) {
        int acc = 0;
        for (int b = 0; b < NSCAN; b++) {
            int x = g_bsums[b];
            g_bsums[b] = acc;
            acc += x;
        }
    }
}
__global__ void k_scan_add() {
    int i = blockIdx.x * 256 + threadIdx.x;
    if (i < NN) {
        int v = g_rowptr[i] + g_bsums[i >> 10];
        g_rowptr[i] = v;
        g_cursor[i] = v;
    }
    if (i == NN) g_rowptr[NN] = EE;
}
__global__ void k_fill(const int* __restrict__ dst, const int* __restrict__ src) {
    int e = blockIdx.x * 256 + threadIdx.x;
    if (e >= EE) return;
    int pos = atomicAdd(&g_cursor[dst[e]], 1);
    g_eid[pos] = e;
    g_esrc[pos] = src[e];
}
__global__ void k_molptr(const int* __restrict__ batch) {
    int g = blockIdx.x * 256 + threadIdx.x;
    if (g > GG) return;
    if (g == GG) { g_molptr[GG] = NN; return; }
    int lo = 0, hi = NN;
    while (lo < hi) {
        int mid = (lo + hi) >> 1;
        if (batch[mid] < g) lo = mid + 1; else hi = mid;
    }
    g_molptr[g] = lo;
}

// ---------------- attention prep ----------------
__global__ void k_v2(const float* __restrict__ We, const float* __restrict__ atte) {
    int w = threadIdx.x >> 5, lane = threadIdx.x & 31;
    float s = 0.f;
    for (int k = lane; k < HH; k += 32) s += atte[k] * We[k * EDIM + w];
    s = warp_sum(s);
    if (lane == 0) {
        g_v[w] = s;
        if (w == 0) g_loopsum[0] = 0.f;
    }
}
__global__ void k_ae(const float* __restrict__ attr) {
    __shared__ float sv[EDIM];
    __shared__ float red[256];
    if (threadIdx.x < EDIM) sv[threadIdx.x] = g_v[threadIdx.x];
    __syncthreads();
    int e = blockIdx.x * 256 + threadIdx.x;
    float a = 0.f;
    if (e < EE) {
        const float* p = attr + (size_t)e * EDIM;
#pragma unroll
        for (int j = 0; j < EDIM; j++) a += p[j] * sv[j];
        g_ae[e] = a;
    }
    red[threadIdx.x] = a;
    __syncthreads();
    for (int st = 128; st; st >>= 1) {
        if (threadIdx.x < st) red[threadIdx.x] += red[threadIdx.x + st];
        __syncthreads();
    }
    if (threadIdx.x == 0) atomicAdd(g_loopsum, red[0]);
}

template <bool C0>
__global__ void k_edge_alpha(const int* __restrict__ src, const int* __restrict__ dst) {
    int e = blockIdx.x * 256 + threadIdx.x;
    if (e >= EE) return;
    float a = g_s[src[e]] + g_d[dst[e]];
    if (C0) a += g_ae[e];
    float sl = C0 ? 0.2f : 0.01f;
    a = a >= 0.f ? a : sl * a;
    g_ew[e] = expf(a);
}

template <bool C0>
__global__ void k_gather(const float* __restrict__ bias, __nv_bfloat16* __restrict__ out3,
                         int dbase, int dcount) {
    int dl = (blockIdx.x * blockDim.x + threadIdx.x) >> 5;
    int lane = threadIdx.x & 31;
    if (dl >= dcount) return;
    int d = dbase + dl;
    int r0 = g_rowptr[d], r1 = g_rowptr[d + 1];
    float se = 0.f;
    for (int i = r0 + lane; i < r1; i += 32) se += g_ew[g_eid[i]];
    se = warp_sum(se);
    float wself = 0.f;
    if (C0) {
        float a = g_s[d] + g_d[d] + g_loopsum[0] * (1.0f / EE);
        a = a >= 0.f ? a : 0.2f * a;
        wself = expf(a);
        se += wself;
    }
    se = __shfl_sync(0xffffffffu, se, 0);
    float inv = 1.f / (se + 1e-16f);

    float4 a0 = make_float4(0.f, 0.f, 0.f, 0.f);
    float4 a1 = make_float4(0.f, 0.f, 0.f, 0.f);
    for (int i = r0; i < r1; i++) {
        int e = g_eid[i];
        int s = g_esrc[i];
        float w = g_ew[e];
        const float4* hs = (const float4*)(g_hW + (size_t)s * HH);
        float4 v = hs[lane];
        a0.x += w * v.x; a0.y += w * v.y; a0.z += w * v.z; a0.w += w * v.w;
        if (lane < 16) {
            float4 v2 = hs[lane + 32];
            a1.x += w * v2.x; a1.y += w * v2.y; a1.z += w * v2.z; a1.w += w * v2.w;
        }
    }
    if (C0) {
        const float4* hs = (const float4*)(g_hW + (size_t)d * HH);
        float4 v = hs[lane];
        a0.x += wself * v.x; a0.y += wself * v.y; a0.z += wself * v.z; a0.w += wself * v.w;
        if (lane < 16) {
            float4 v2 = hs[lane + 32];
            a1.x += wself * v2.x; a1.y += wself * v2.y; a1.z += wself * v2.z; a1.w += wself * v2.w;
        }
    }
    size_t rowb = (size_t)d * H3;
    {
        int c0 = lane * 4;
        float x0 = a0.x * inv + bias[c0], x1 = a0.y * inv + bias[c0 + 1];
        float x2 = a0.z * inv + bias[c0 + 2], x3 = a0.w * inv + bias[c0 + 3];
        x0 = x0 > 0.f ? x0 : expm1f(x0); x1 = x1 > 0.f ? x1 : expm1f(x1);
        x2 = x2 > 0.f ? x2 : expm1f(x2); x3 = x3 > 0.f ? x3 : expm1f(x3);
        store_split4(out3 + rowb + c0, x0, x1, x2, x3);
    }
    if (lane < 16) {
        int c0 = 128 + lane * 4;
        float x0 = a1.x * inv + bias[c0], x1 = a1.y * inv + bias[c0 + 1];
        float x2 = a1.z * inv + bias[c0 + 2], x3 = a1.w * inv + bias[c0 + 3];
        x0 = x0 > 0.f ? x0 : expm1f(x0); x1 = x1 > 0.f ? x1 : expm1f(x1);
        x2 = x2 > 0.f ? x2 : expm1f(x2); x3 = x3 > 0.f ? x3 : expm1f(x3);
        store_split4(out3 + rowb + c0, x0, x1, x2, x3);
    }
}

// warp per graph: segment-sum pool + relu + split
__global__ void k_pool_seg() {
    int g = (blockIdx.x * blockDim.x + threadIdx.x) >> 5;
    int lane = threadIdx.x & 31;
    if (g >= GG) return;
    int p0 = g_molptr[g], p1 = g_molptr[g + 1];
    float4 a0 = make_float4(0.f, 0.f, 0.f, 0.f);
    float4 a1 = make_float4(0.f, 0.f, 0.f, 0.f);
    for (int i = p0; i < p1; i++) {
        const float4* xr = (const float4*)(g_x + (size_t)i * HH);
        float4 v = xr[lane];
        a0.x += v.x; a0.y += v.y; a0.z += v.z; a0.w += v.w;
        if (lane < 16) {
            float4 v2 = xr[lane + 32];
            a1.x += v2.x; a1.y += v2.y; a1.z += v2.z; a1.w += v2.w;
        }
    }
    a0.x = fmaxf(a0.x, 0.f); a0.y = fmaxf(a0.y, 0.f);
    a0.z = fmaxf(a0.z, 0.f); a0.w = fmaxf(a0.w, 0.f);
    size_t rowb = (size_t)g * H3;
    ((float4*)(g_out + (size_t)g * HH))[lane] = a0;
    store_split4(g_a3m + rowb + lane * 4, a0.x, a0.y, a0.z, a0.w);
    if (lane < 16) {
        a1.x = fmaxf(a1.x, 0.f); a1.y = fmaxf(a1.y, 0.f);
        a1.z = fmaxf(a1.z, 0.f); a1.w = fmaxf(a1.w, 0.f);
        ((float4*)(g_out + (size_t)g * HH))[lane + 32] = a1;
        store_split4(g_a3m + rowb + 128 + lane * 4, a1.x, a1.y, a1.z, a1.w);
    }
}

// warp per graph: mol GAT gather + ELU + bias + split -> a3m2
__global__ void k_molgather(const float* __restrict__ mol_b) {
    int g = (blockIdx.x * blockDim.x + threadIdx.x) >> 5;
    int lane = threadIdx.x & 31;
    if (g >= GG) return;
    int p0 = g_molptr[g], p1 = g_molptr[g + 1];
    float dg = g_dmol[g];
    float se = 0.f;
    for (int i = p0 + lane; i < p1; i += 32) {
        float a = g_smol[i] + dg;
        a = a >= 0.f ? a : 0.01f * a;
        se += expf(a);
    }
    se = warp_sum(se);
    se = __shfl_sync(0xffffffffu, se, 0);
    float inv = 1.f / (se + 1e-16f);
    float4 a0 = make_float4(0.f, 0.f, 0.f, 0.f);
    float4 a1 = make_float4(0.f, 0.f, 0.f, 0.f);
    for (int i = p0; i < p1; i++) {
        float a = g_smol[i] + dg;
        a = a >= 0.f ? a : 0.01f * a;
        float w = expf(a);
        const float4* hs = (const float4*)(g_hW + (size_t)i * HH);
        float4 v = hs[lane];
        a0.x += w * v.x; a0.y += w * v.y; a0.z += w * v.z; a0.w += w * v.w;
        if (lane < 16) {
            float4 v2 = hs[lane + 32];
            a1.x += w * v2.x; a1.y += w * v2.y; a1.z += w * v2.z; a1.w += w * v2.w;
        }
    }
    size_t rowb = (size_t)g * H3;
    {
        int c0 = lane * 4;
        float x0 = a0.x * inv + mol_b[c0], x1 = a0.y * inv + mol_b[c0 + 1];
        float x2 = a0.z * inv + mol_b[c0 + 2], x3 = a0.w * inv + mol_b[c0 + 3];
        x0 = x0 > 0.f ? x0 : expm1f(x0); x1 = x1 > 0.f ? x1 : expm1f(x1);
        x2 = x2 > 0.f ? x2 : expm1f(x2); x3 = x3 > 0.f ? x3 : expm1f(x3);
        store_split4(g_a3m2 + rowb + c0, x0, x1, x2, x3);
    }
    if (lane < 16) {
        int c0 = 128 + lane * 4;
        float x0 = a1.x * inv + mol_b[c0], x1 = a1.y * inv + mol_b[c0 + 1];
        float x2 = a1.z * inv + mol_b[c0 + 2], x3 = a1.w * inv + mol_b[c0 + 3];
        x0 = x0 > 0.f ? x0 : expm1f(x0); x1 = x1 > 0.f ? x1 : expm1f(x1);
        x2 = x2 > 0.f ? x2 : expm1f(x2); x3 = x3 > 0.f ? x3 : expm1f(x3);
        store_split4(g_a3m2 + rowb + c0, x0, x1, x2, x3);
    }
}

__global__ void k_final(const float* __restrict__ W, const float* __restrict__ b,
                        float* __restrict__ out) {
    int gw = (blockIdx.x * blockDim.x + threadIdx.x) >> 5;
    int lane = threadIdx.x & 31;
    if (gw >= GG) return;
    float s = 0.f;
    for (int k = lane; k < HH; k += 32) s += g_out[gw * HH + k] * W[k];
    s = warp_sum(s);
    if (lane == 0) out[gw] = s + b[0];
}

// ---------------- host ----------------
static inline int cdiv(int a, int b) { return (a + b - 1) / b; }

extern "C" void kernel_launch(void* const* d_in, const int* in_sizes, int n_in,
                              void* d_out, int out_size) {
    const float* x_in = (const float*)d_in[0];
    const int* eidx = (const int*)d_in[1];
    const float* eattr = (const float*)d_in[2];
    const int* batch = (const int*)d_in[3];
    const float* lin1_W = (const float*)d_in[4];
    const float* lin1_b = (const float*)d_in[5];
    const float* conv0_W = (const float*)d_in[6];
    const float* conv0_att_s = (const float*)d_in[7];
    const float* conv0_att_d = (const float*)d_in[8];
    const float* conv0_We = (const float*)d_in[9];
    const float* conv0_att_e = (const float*)d_in[10];
    const float* conv0_b = (const float*)d_in[11];
    const float* convs_W = (const float*)d_in[12];
    const float* convs_att_s = (const float*)d_in[13];
    const float* convs_att_d = (const float*)d_in[14];
    const float* convs_b = (const float*)d_in[15];
    const float* gru_Wih = (const float*)d_in[16];
    const float* gru_Whh = (const float*)d_in[17];
    const float* gru_bih = (const float*)d_in[18];
    const float* gru_bhh = (const float*)d_in[19];
    const float* mol_Wsrc = (const float*)d_in[20];
    const float* mol_Wdst = (const float*)d_in[21];
    const float* mol_att_s = (const float*)d_in[22];
    const float* mol_att_d = (const float*)d_in[23];
    const float* mol_b = (const float*)d_in[24];
    const float* mgru_Wih = (const float*)d_in[25];
    const float* mgru_Whh = (const float*)d_in[26];
    const float* mgru_bih = (const float*)d_in[27];
    const float* mgru_bhh = (const float*)d_in[28];
    const float* lin2_W = (const float*)d_in[29];
    const float* lin2_b = (const float*)d_in[30];

    const int* src = eidx;
    const int* dst = eidx + EE;

    float *px, *phW, *pgh, *ps, *pd, *pout, *psmol, *pdmol;
    float *bp_ih, *bp_hh, *bp_mi, *bp_mh;
    int* pdeg;
    cudaGetSymbolAddress((void**)&px, g_x);
    cudaGetSymbolAddress((void**)&phW, g_hW);
    cudaGetSymbolAddress((void**)&pgh, g_gh);
    cudaGetSymbolAddress((void**)&ps, g_s);
    cudaGetSymbolAddress((void**)&pd, g_d);
    cudaGetSymbolAddress((void**)&pout, g_out);
    cudaGetSymbolAddress((void**)&psmol, g_smol);
    cudaGetSymbolAddress((void**)&pdmol, g_dmol);
    cudaGetSymbolAddress((void**)&pdeg, g_deg);
    cudaGetSymbolAddress((void**)&bp_ih, g_bp_ih);
    cudaGetSymbolAddress((void**)&bp_hh, g_bp_hh);
    cudaGetSymbolAddress((void**)&bp_mi, g_bp_mi);
    cudaGetSymbolAddress((void**)&bp_mh, g_bp_mh);
    __nv_bfloat16 *a3, *a3b, *b3, *b3wd, *b3wi, *b3wh, *a3m, *a3m2;
    cudaGetSymbolAddress((void**)&a3, g_a3);
    cudaGetSymbolAddress((void**)&a3b, g_a3b);
    cudaGetSymbolAddress((void**)&b3, g_b3);
    cudaGetSymbolAddress((void**)&b3wd, g_b3wd);
    cudaGetSymbolAddress((void**)&b3wi, g_b3wi);
    cudaGetSymbolAddress((void**)&b3wh, g_b3wh);
    cudaGetSymbolAddress((void**)&a3m, g_a3m);
    cudaGetSymbolAddress((void**)&a3m2, g_a3m2);

    cudaFuncSetAttribute(bgemm<1, false, false, false>, cudaFuncAttributeMaxDynamicSharedMemorySize, BG_SMEM);
    cudaFuncSetAttribute(bgemm<2, true, false, false>, cudaFuncAttributeMaxDynamicSharedMemorySize, BG_SMEM);
    cudaFuncSetAttribute(bgemm<0, false, true, false>, cudaFuncAttributeMaxDynamicSharedMemorySize, BG_SMEM);
    cudaFuncSetAttribute(bgemm<0, false, false, true>, cudaFuncAttributeMaxDynamicSharedMemorySize, BG_SMEM);

    cudaStream_t s2;
    cudaStreamCreate(&s2);
    cudaEvent_t ev[32];
    for (int i = 0; i < 32; i++) cudaEventCreateWithFlags(&ev[i], cudaEventDisableTiming);
#define REC0(i) cudaEventRecord(ev[i], 0)
#define RECS(i) cudaEventRecord(ev[i], s2)
#define W0(i) cudaStreamWaitEvent(0, ev[i], 0)
#define WS(i) cudaStreamWaitEvent(s2, ev[i], 0)

    auto bg1 = [&](const __nv_bfloat16* A, const __nv_bfloat16* B, const float* bias,
                   float* C, int M, int Nc, int K3, cudaStream_t st) {
        bgemm<1, false, false, false><<<dim3(Nc / BN, cdiv(M, 128)), 256, BG_SMEM, st>>>(
            A, B, bias, C, nullptr, nullptr, nullptr, nullptr, nullptr, nullptr, nullptr,
            M, Nc, K3, 0);
    };
    auto bgD = [&](const __nv_bfloat16* A, const __nv_bfloat16* B, float* C,
                   const float* u, const float* w, float* ou, float* ow,
                   int M, int Nc, int K3) {
        bgemm<0, false, true, false><<<dim3(Nc / BN, cdiv(M, 128)), 256, BG_SMEM>>>(
            A, B, nullptr, C, nullptr, u, w, ou, ow, nullptr, nullptr, M, Nc, K3, 0);
    };
    // GRU-fused GEMM over node rows [rb, rb+rows)
    auto bgGRU = [&](const __nv_bfloat16* A, const __nv_bfloat16* B, const float* bias_p,
                     const float* ghp, float* xb, __nv_bfloat16* out3, int M,
                     int rb, int rows, cudaStream_t st) {
        bgemm<0, false, false, true><<<dim3(H3 / BN, cdiv(rows, 128)), 256, BG_SMEM, st>>>(
            A, B, bias_p, nullptr, out3, nullptr, nullptr, nullptr, nullptr, ghp, xb,
            M, H3, H3, rb);
    };

    const int H1ROWS = NN - H0ROWS;

    // ---- main prologue (slot 3 = bgD profiled) ----
    REC0(0);
    k_splitA<<<cdiv(NN * CC, 256), 256>>>(x_in, a3b);
    k_splitB2<<<cdiv(HH * CC + HH * HH, 256), 256>>>(lin1_W, b3wd, conv0_W, b3);
    bgemm<2, true, false, false><<<dim3(HH / BN, cdiv(NN, 128)), 256, BG_SMEM>>>(
        a3b, b3wd, lin1_b, px, a3, nullptr, nullptr, nullptr, nullptr, nullptr, nullptr,
        NN, HH, 3 * CC, 0);
    REC0(1);  // a3 ready
    bgD(a3, b3, phW, conv0_att_s, conv0_att_d, ps, pd, NN, HH, H3);  // PROFILED

    // ---- s2: ae + CSR + conv0 gh chain ----
    WS(0);
    k_v2<<<1, 512, 0, s2>>>(conv0_We, conv0_att_e);
    k_ae<<<cdiv(EE, 256), 256, 0, s2>>>(eattr);
    RECS(2);  // ae ready
    k_zero_int<<<cdiv(NN, 256), 256, 0, s2>>>(pdeg, NN);
    k_hist<<<cdiv(EE, 256), 256, 0, s2>>>(dst);
    k_scan_block<<<NSCAN, SCAN_BLK, 0, s2>>>();
    k_scan_mid<<<1, 32, 0, s2>>>();
    k_scan_add<<<cdiv(NN + 1, 256), 256, 0, s2>>>();
    k_fill<<<cdiv(EE, 256), 256, 0, s2>>>(dst, src);
    k_molptr<<<cdiv(GG + 1, 256), 256, 0, s2>>>(batch);
    RECS(3);  // CSR ready
    WS(1);
    k_splitB_perm<<<cdiv(H3 * HH, 256), 256, 0, s2>>>(gru_Whh, b3wh);
    k_permbias<<<1, H3, 0, s2>>>(gru_bhh, bp_hh, gru_bih, bp_ih);
    bg1(a3, b3wh, bp_hh, pgh, NN, H3, H3, s2);
    RECS(4);  // gh ready

    // ---- conv0 main chain: gather/GRU half-pipelined ----
    W0(2);
    k_edge_alpha<true><<<cdiv(EE, 256), 256>>>(src, dst);
    W0(3);
    k_splitB_perm<<<cdiv(H3 * HH, 256), 256>>>(gru_Wih, b3wi);
    k_gather<true><<<cdiv(H0ROWS * 32, 256), 256>>>(conv0_b, a3b, 0, H0ROWS);
    REC0(5);
    k_gather<true><<<cdiv(H1ROWS * 32, 256), 256>>>(conv0_b, a3b, H0ROWS, H1ROWS);
    // s2: GRU half0 while main gathers half1
    WS(5);
    bgGRU(a3b, b3wi, bp_ih, pgh, px, a3, NN, 0, H0ROWS, s2);
    RECS(6);
    W0(4);
    bgGRU(a3b, b3wi, bp_ih, pgh, px, a3, NN, H0ROWS, H1ROWS, 0);
    W0(6);
    REC0(7);  // layer fully done

    // ---- remaining atom conv layers ----
    for (int l = 0; l < 2; l++) {
        const int eL = 7 + 6 * l;
        // s2: gh chain + GRU half0
        WS(eL);
        k_splitB_perm<<<cdiv(H3 * HH, 256), 256, 0, s2>>>(gru_Whh + (size_t)(l + 1) * H3 * HH, b3wh);
        k_permbias<<<1, H3, 0, s2>>>(gru_bhh + (l + 1) * H3, bp_hh, gru_bih + (l + 1) * H3, bp_ih);
        bg1(a3, b3wh, bp_hh, pgh, NN, H3, H3, s2);
        RECS(eL + 1);  // gh ready
        // main: attention chain
        k_splitB<<<cdiv(HH * HH, 256), 256>>>(convs_W + (size_t)l * HH * HH, b3, HH, HH);
        k_zero2<<<cdiv(NN, 256), 256>>>(ps, pd, NN, NN);
        bgD(a3, b3, phW, convs_att_s + l * HH, convs_att_d + l * HH, ps, pd, NN, HH, H3);
        k_edge_alpha<false><<<cdiv(EE, 256), 256>>>(src, dst);
        k_splitB_perm<<<cdiv(H3 * HH, 256), 256>>>(gru_Wih + (size_t)(l + 1) * H3 * HH, b3wi);
        k_gather<false><<<cdiv(H0ROWS * 32, 256), 256>>>(convs_b + l * HH, a3b, 0, H0ROWS);
        REC0(eL + 2);
        k_gather<false><<<cdiv(H1ROWS * 32, 256), 256>>>(convs_b + l * HH, a3b, H0ROWS, H1ROWS);
        WS(eL + 2);
        bgGRU(a3b, b3wi, bp_ih, pgh, px, a3, NN, 0, H0ROWS, s2);
        RECS(eL + 3);
        W0(eL + 1);
        bgGRU(a3b, b3wi, bp_ih, pgh, px, a3, NN, H0ROWS, H1ROWS, 0);
        W0(eL + 3);
        REC0(eL + 6);  // 13, 19
    }

    // ---- molecule readout ----
    WS(19);
    k_pool_seg<<<cdiv(GG * 32, 256), 256, 0, s2>>>();
    k_splitB<<<cdiv(HH * HH, 256), 256, 0, s2>>>(mol_Wdst, b3wd, HH, HH);
    k_splitB_perm<<<cdiv(H3 * HH, 256), 256, 0, s2>>>(mgru_Wih, b3wi);
    k_splitB_perm<<<cdiv(H3 * HH, 256), 256, 0, s2>>>(mgru_Whh, b3wh);
    k_permbias<<<1, H3, 0, s2>>>(mgru_bih, bp_mi, mgru_bhh, bp_mh);
    RECS(20);
    k_splitB<<<cdiv(HH * HH, 256), 256>>>(mol_Wsrc, b3, HH, HH);
    k_zero2<<<cdiv(NN, 256), 256>>>(psmol, psmol, NN, 0);
    bgD(a3, b3, phW, mol_att_s, nullptr, psmol, nullptr, NN, HH, H3);
    W0(20);

    for (int t = 0; t < 2; t++) {
        REC0(21 + 2 * t);
        WS(21 + 2 * t);
        bg1(a3m, b3wh, bp_mh, pgh, GG, H3, H3, s2);
        RECS(22 + 2 * t);
        k_zero2<<<cdiv(GG, 256), 256>>>(pdmol, pdmol, GG, 0);
        bgD(a3m, b3wd, nullptr, mol_att_d, nullptr, pdmol, nullptr, GG, HH, H3);
        k_molgather<<<cdiv(GG * 32, 256), 256>>>(mol_b);
        W0(22 + 2 * t);
        bgGRU(a3m2, b3wi, bp_mi, pgh, pout, a3m, GG, 0, GG, 0);
    }

    k_final<<<cdiv(GG * 32, 256), 256>>>(lin2_W, lin2_b, (float*)d_out);
#undef REC0
#undef RECS
#undef W0
#undef WS
}

// round 14
// speedup vs baseline: 1.2013x; 1.2013x over previous
#include <cuda_runtime.h>
#include <cuda_fp16.h>
#include <math.h>
#include <stdint.h>

#define NN 50000
#define EE 800000
#define CC 64
#define HH 192
#define H3 576
#define EDIM 16
#define GG 2048
#define K2A (2 * HH)  // 384: fp16x2 K for H-sized GEMMs

// ---------------- scratch ----------------
__device__ __align__(16) float g_x[NN * HH];
__device__ __align__(16) float g_hW[NN * HH];
__device__ __align__(16) float g_gh[NN * H3];
__device__ float g_s[NN];
__device__ float g_d[NN];
__device__ float g_ae[EE];
__device__ float g_ew[EE];
__device__ float g_v[EDIM];
__device__ float g_loopsum[1];
__device__ __align__(16) float g_out[GG * HH];
__device__ float g_smol[NN];
__device__ float g_dmol[GG];
__device__ float g_bp_ih[H3];
__device__ float g_bp_hh[H3];
__device__ float g_bp_mi[H3];
__device__ float g_bp_mh[H3];
// CSR
__device__ int g_deg[NN];
__device__ int g_cursor[NN];
__device__ int g_rowptr[NN + 1];
__device__ int g_eid[EE];
__device__ int g_esrc[EE];
__device__ int g_bsums[64];
__device__ int g_molptr[GG + 1];
// fp16x2 split buffers (A-mode: [hi|lo] exact; B-mode: [hi|hi] rounded)
__device__ __align__(16) __half g_a3[(size_t)NN * K2A];
__device__ __align__(16) __half g_a3b[(size_t)NN * K2A];
__device__ __align__(16) __half g_b3[(size_t)HH * K2A];
__device__ __align__(16) __half g_b3wd[(size_t)HH * K2A];
__device__ __align__(16) __half g_b3wi[(size_t)H3 * K2A];
__device__ __align__(16) __half g_b3wh[(size_t)H3 * K2A];
__device__ __align__(16) __half g_a3m[(size_t)GG * K2A];
__device__ __align__(16) __half g_a3m2[(size_t)GG * K2A];

// ---------------- helpers ----------------
__device__ __forceinline__ float warp_sum(float v) {
#pragma unroll
    for (int o = 16; o; o >>= 1) v += __shfl_down_sync(0xffffffffu, v, o);
    return v;
}
__device__ __forceinline__ float sigm(float x) { return 1.f / (1.f + expf(-x)); }
__device__ __forceinline__ uint32_t smem_u32(const void* p) {
    uint32_t a;
    asm("{ .reg .u64 t; cvta.to.shared.u64 t, %1; cvt.u32.u64 %0, t; }" : "=r"(a) : "l"(p));
    return a;
}
__device__ __forceinline__ void cp16(uint32_t s, const void* g) {
    asm volatile("cp.async.cg.shared.global [%0], [%1], 16;" :: "r"(s), "l"(g));
}
__device__ __forceinline__ void ldsm4(uint32_t& r0, uint32_t& r1, uint32_t& r2, uint32_t& r3,
                                      uint32_t addr) {
    asm volatile("ldmatrix.sync.aligned.m8n8.x4.shared.b16 {%0,%1,%2,%3}, [%4];"
                 : "=r"(r0), "=r"(r1), "=r"(r2), "=r"(r3) : "r"(addr));
}
__device__ __forceinline__ void mma16816(float* d, const uint32_t* a, const uint32_t* b) {
    asm volatile(
        "mma.sync.aligned.m16n8k16.row.col.f32.f16.f16.f32 "
        "{%0,%1,%2,%3}, {%4,%5,%6,%7}, {%8,%9}, {%0,%1,%2,%3};"
        : "+f"(d[0]), "+f"(d[1]), "+f"(d[2]), "+f"(d[3])
        : "r"(a[0]), "r"(a[1]), "r"(a[2]), "r"(a[3]), "r"(b[0]), "r"(b[1]));
}
__device__ __forceinline__ void redf(float* p, float v) {
    asm volatile("red.global.add.f32 [%0], %1;" :: "l"(p), "f"(v) : "memory");
}
__device__ __forceinline__ unsigned short hb(__half h) {
    return *reinterpret_cast<unsigned short*>(&h);
}
// A-mode fp16x2 store: hi (4 vals) at [0], lo at [+HH]
__device__ __forceinline__ void store_split4(__half* base, float v0, float v1,
                                             float v2, float v3) {
    __half h0 = __float2half_rn(v0), h1 = __float2half_rn(v1);
    __half h2 = __float2half_rn(v2), h3 = __float2half_rn(v3);
    __half l0 = __float2half_rn(v0 - __half2float(h0));
    __half l1 = __float2half_rn(v1 - __half2float(h1));
    __half l2 = __float2half_rn(v2 - __half2float(h2));
    __half l3 = __float2half_rn(v3 - __half2float(h3));
    uint2 hp, lp;
    hp.x = ((uint32_t)hb(h1) << 16) | hb(h0);
    hp.y = ((uint32_t)hb(h3) << 16) | hb(h2);
    lp.x = ((uint32_t)hb(l1) << 16) | hb(l0);
    lp.y = ((uint32_t)hb(l3) << 16) | hb(l2);
    *(uint2*)(base) = hp;
    *(uint2*)(base + HH) = lp;
}

// ===== fp16 mma.sync NT GEMM: 128x96 tile, 256 threads, 2 CTAs/SM, 3-stage pipeline =====
#define BN 96
#define A_BUF 16384
#define B_BUF 12288
#define BG_SMEM (3 * A_BUF + 3 * B_BUF)
template <int EPI, bool SPLIT, bool DOT, bool GRUF>
__global__ void __launch_bounds__(256, 2)
bgemm(const __half* __restrict__ A3, const __half* __restrict__ B3,
      const float* __restrict__ bias, float* __restrict__ C,
      __half* __restrict__ C3,
      const float* __restrict__ u, const float* __restrict__ w,
      float* __restrict__ ou, float* __restrict__ ow,
      const float* __restrict__ gh, float* __restrict__ xb,
      int M, int Nc, int K3) {
    extern __shared__ __align__(16) char dsm[];
    const int tid = threadIdx.x;
    const int lane = tid & 31, wid = tid >> 5;
    const int wm = wid & 3, wn = wid >> 2;
    const int row0 = blockIdx.y * 128, col0 = blockIdx.x * BN;
    const uint32_t aB = smem_u32(dsm);
    const uint32_t bB = aB + 3 * A_BUF;

    float acc[2][6][4] = {};
    const int nc = K3 >> 6;

    auto issue = [&](int c, int buf) {
        const uint32_t ab = aB + buf * A_BUF;
        const uint32_t bb = bB + buf * B_BUF;
#pragma unroll
        for (int q = 0; q < 4; q++) {
            int idx = q * 256 + tid;
            int r = idx >> 3, kc = idx & 7;
            int grow = row0 + r;
            grow = grow < M ? grow : M - 1;
            cp16(ab + (uint32_t)(r * 128 + ((kc * 16) ^ ((r & 7) << 4))),
                 A3 + (size_t)grow * K3 + c * 64 + kc * 8);
        }
#pragma unroll
        for (int q = 0; q < 3; q++) {
            int idx = q * 256 + tid;
            int r = idx >> 3, kc = idx & 7;
            cp16(bb + (uint32_t)(r * 128 + ((kc * 16) ^ ((r & 7) << 4))),
                 B3 + (size_t)(col0 + r) * K3 + c * 64 + kc * 8);
        }
        asm volatile("cp.async.commit_group;" ::: "memory");
    };

    const int a_r = wm * 32 + ((lane >> 3) & 1) * 8 + (lane & 7);
    const int a_kb = ((lane >> 4) & 1) * 16;
    const int b_r = wn * 48 + ((lane >> 4) & 1) * 8 + (lane & 7);
    const int b_kb = ((lane >> 3) & 1) * 16;

    issue(0, 0);
    issue(1, 1);
    for (int c = 0; c < nc; c++) {
        const int buf = c % 3;
        if (c + 2 < nc) {
            issue(c + 2, (c + 2) % 3);
            asm volatile("cp.async.wait_group 2;" ::: "memory");
        } else if (c + 1 < nc) {
            asm volatile("cp.async.wait_group 1;" ::: "memory");
        } else {
            asm volatile("cp.async.wait_group 0;" ::: "memory");
        }
        __syncthreads();
        const uint32_t ab = aB + buf * A_BUF;
        const uint32_t bb = bB + buf * B_BUF;
#pragma unroll
        for (int ks = 0; ks < 4; ks++) {
            uint32_t af[2][4], bfr[3][4];
#pragma unroll
            for (int mi = 0; mi < 2; mi++) {
                int r = a_r + mi * 16;
                ldsm4(af[mi][0], af[mi][1], af[mi][2], af[mi][3],
                      ab + (uint32_t)(r * 128 + ((ks * 32 + a_kb) ^ ((r & 7) << 4))));
            }
#pragma unroll
            for (int p = 0; p < 3; p++) {
                int r = b_r + p * 16;
                ldsm4(bfr[p][0], bfr[p][1], bfr[p][2], bfr[p][3],
                      bb + (uint32_t)(r * 128 + ((ks * 32 + b_kb) ^ ((r & 7) << 4))));
            }
#pragma unroll
            for (int mi = 0; mi < 2; mi++)
#pragma unroll
                for (int ni = 0; ni < 6; ni++) {
                    uint32_t b2[2] = {bfr[ni >> 1][(ni & 1) * 2], bfr[ni >> 1][(ni & 1) * 2 + 1]};
                    mma16816(acc[mi][ni], af[mi], b2);
                }
        }
        __syncthreads();
    }

    const int qr = lane >> 2, qc = (lane & 3) * 2;

    if (GRUF) {
        float* S = (float*)dsm;
        const int ST = 100;
        const int r_l = tid >> 3;
        const int f0 = (tid & 7) * 4;
#pragma unroll
        for (int mi = 0; mi < 2; mi++) {
#pragma unroll
            for (int half = 0; half < 2; half++) {
#pragma unroll
                for (int ni = 0; ni < 6; ni++) {
                    int cl = wn * 48 + ni * 8 + qc;
                    float v0 = acc[mi][ni][half * 2 + 0] + bias[col0 + cl];
                    float v1 = acc[mi][ni][half * 2 + 1] + bias[col0 + cl + 1];
                    *(float2*)&S[(wm * 8 + qr) * ST + cl] = make_float2(v0, v1);
                }
                __syncthreads();
                int row = row0 + (r_l >> 3) * 32 + mi * 16 + half * 8 + (r_l & 7);
                if (row < M) {
                    const float* Sr = &S[r_l * ST + 3 * f0];
                    const float* ghr = gh + (size_t)row * Nc + col0 + 3 * f0;
                    int fg = col0 / 3 + f0;
                    float4 xv = *(const float4*)(xb + (size_t)row * HH + fg);
                    float xo[4] = {xv.x, xv.y, xv.z, xv.w};
                    float o[4];
#pragma unroll
                    for (int q = 0; q < 4; q++) {
                        float gir = Sr[3 * q], giz = Sr[3 * q + 1], gin = Sr[3 * q + 2];
                        float hr = ghr[3 * q], hz = ghr[3 * q + 1], hn = ghr[3 * q + 2];
                        float r = sigm(gir + hr);
                        float z = sigm(giz + hz);
                        float n = tanhf(gin + r * hn);
                        float v = (1.f - z) * n + z * xo[q];
                        o[q] = v > 0.f ? v : 0.f;
                    }
                    *(float4*)(xb + (size_t)row * HH + fg) = make_float4(o[0], o[1], o[2], o[3]);
                    store_split4(C3 + (size_t)row * K2A + fg, o[0], o[1], o[2], o[3]);
                }
                __syncthreads();
            }
        }
        return;
    }

#pragma unroll
    for (int mi = 0; mi < 2; mi++) {
#pragma unroll
        for (int half = 0; half < 2; half++) {
            int row = row0 + wm * 32 + mi * 16 + half * 8 + qr;
            bool ok = row < M;
            float p_s = 0.f, p_d = 0.f;
#pragma unroll
            for (int ni = 0; ni < 6; ni++) {
                int cc0 = col0 + wn * 48 + ni * 8 + qc;
                float v0 = acc[mi][ni][half * 2 + 0];
                float v1 = acc[mi][ni][half * 2 + 1];
                if (EPI >= 1) { v0 += bias[cc0]; v1 += bias[cc0 + 1]; }
                if (EPI == 2) {
                    v0 = v0 > 0.f ? v0 : 0.01f * v0;
                    v1 = v1 > 0.f ? v1 : 0.01f * v1;
                }
                if (DOT) {
                    p_s += v0 * u[cc0] + v1 * u[cc0 + 1];
                    if (w) p_d += v0 * w[cc0] + v1 * w[cc0 + 1];
                }
                if (ok && C) *(float2*)(C + (size_t)row * Nc + cc0) = make_float2(v0, v1);
                if (SPLIT && ok) {
                    size_t base = (size_t)row * (2 * Nc) + cc0;
                    __half h0 = __float2half_rn(v0);
                    __half l0 = __float2half_rn(v0 - __half2float(h0));
                    __half h1 = __float2half_rn(v1);
                    __half l1 = __float2half_rn(v1 - __half2float(h1));
                    C3[base] = h0; C3[base + 1] = h1;
                    C3[base + Nc] = l0; C3[base + Nc + 1] = l1;
                }
            }
            if (DOT) {
                p_s += __shfl_xor_sync(0xffffffffu, p_s, 1);
                p_s += __shfl_xor_sync(0xffffffffu, p_s, 2);
                if (w) {
                    p_d += __shfl_xor_sync(0xffffffffu, p_d, 1);
                    p_d += __shfl_xor_sync(0xffffffffu, p_d, 2);
                }
                if (ok && (lane & 3) == 0) {
                    redf(ou + row, p_s);
                    if (w) redf(ow + row, p_d);
                }
            }
        }
    }
}

// ---------------- split kernels ----------------
// A-mode split of x_in: [hi|lo]; also zeroes g_s/g_d
__global__ void k_splitA(const float* __restrict__ X, __half* __restrict__ Y) {
    int idx = blockIdx.x * 256 + threadIdx.x;
    if (idx < NN) { g_s[idx] = 0.f; g_d[idx] = 0.f; }
    if (idx >= NN * CC) return;
    int r = idx / CC, j = idx % CC;
    float v = X[idx];
    __half hi = __float2half_rn(v);
    __half lo = __float2half_rn(v - __half2float(hi));
    size_t b = (size_t)r * 2 * CC + j;
    Y[b] = hi; Y[b + CC] = lo;
}
// B-mode split: [hi|hi]
__global__ void k_splitB(const float* __restrict__ X, __half* __restrict__ Y,
                         int rows, int K) {
    int idx = blockIdx.x * 256 + threadIdx.x;
    if (idx >= rows * K) return;
    int r = idx / K, j = idx % K;
    __half hi = __float2half_rn(X[idx]);
    size_t b = (size_t)r * 2 * K + j;
    Y[b] = hi; Y[b + K] = hi;
}
__global__ void k_splitB2(const float* __restrict__ X1, __half* __restrict__ Y1,
                          const float* __restrict__ X2, __half* __restrict__ Y2) {
    int idx = blockIdx.x * 256 + threadIdx.x;
    const int n1 = HH * CC;
    if (idx < n1) {
        int r = idx / CC, j = idx % CC;
        __half hi = __float2half_rn(X1[idx]);
        size_t b = (size_t)r * 2 * CC + j;
        Y1[b] = hi; Y1[b + CC] = hi;
    }
    int i2 = idx - n1;
    if (i2 >= 0 && i2 < HH * HH) {
        int r = i2 / HH, j = i2 % HH;
        __half hi = __float2half_rn(X2[i2]);
        size_t b = (size_t)r * 2 * HH + j;
        Y2[b] = hi; Y2[b + HH] = hi;
    }
}
// gate-permuted B split: row j=g*192+f -> row 3f+g, duplicated
__global__ void k_splitB_perm(const float* __restrict__ X, __half* __restrict__ Y) {
    int idx = blockIdx.x * 256 + threadIdx.x;
    if (idx >= H3 * HH) return;
    int j = idx / HH, k = idx % HH;
    int g = j / HH, f = j % HH;
    int rp = 3 * f + g;
    __half hi = __float2half_rn(X[idx]);
    size_t b = (size_t)rp * K2A + k;
    Y[b] = hi; Y[b + HH] = hi;
}
__global__ void k_permbias(const float* __restrict__ b1, float* __restrict__ o1,
                           const float* __restrict__ b2, float* __restrict__ o2) {
    int j = threadIdx.x;
    int g = j / HH, f = j % HH;
    o1[3 * f + g] = b1[j];
    o2[3 * f + g] = b2[j];
}

// ---------------- CSR build ----------------
__global__ void k_zero_int(int* p, int n) {
    int i = blockIdx.x * 256 + threadIdx.x;
    if (i < n) p[i] = 0;
}
__global__ void k_zero2(float* a, float* b, int na, int nb) {
    int i = blockIdx.x * 256 + threadIdx.x;
    if (i < na) a[i] = 0.f;
    if (i < nb) b[i] = 0.f;
}
__global__ void k_hist(const int* __restrict__ dst) {
    int e = blockIdx.x * 256 + threadIdx.x;
    if (e < EE) atomicAdd(&g_deg[dst[e]], 1);
}
#define SCAN_BLK 1024
#define NSCAN 49
__global__ void k_scan_block() {
    __shared__ int s[SCAN_BLK];
    int b = blockIdx.x, t = threadIdx.x;
    int i = b * SCAN_BLK + t;
    int v = (i < NN) ? g_deg[i] : 0;
    s[t] = v;
    __syncthreads();
    for (int off = 1; off < SCAN_BLK; off <<= 1) {
        int x = (t >= off) ? s[t - off] : 0;
        __syncthreads();
        s[t] += x;
        __syncthreads();
    }
    if (i < NN) g_rowptr[i] = s[t] - v;
    if (t == SCAN_BLK - 1) g_bsums[b] = s[t];
}
__global__ void k_scan_mid() {
    if (threadIdx.x == 0) {
        int acc = 0;
        for (int b = 0; b < NSCAN; b++) {
            int x = g_bsums[b];
            g_bsums[b] = acc;
            acc += x;
        }
    }
}
__global__ void k_scan_add() {
    int i = blockIdx.x * 256 + threadIdx.x;
    if (i < NN) {
        int v = g_rowptr[i] + g_bsums[i >> 10];
        g_rowptr[i] = v;
        g_cursor[i] = v;
    }
    if (i == NN) g_rowptr[NN] = EE;
}
__global__ void k_fill(const int* __restrict__ dst, const int* __restrict__ src) {
    int e = blockIdx.x * 256 + threadIdx.x;
    if (e >= EE) return;
    int pos = atomicAdd(&g_cursor[dst[e]], 1);
    g_eid[pos] = e;
    g_esrc[pos] = src[e];
}
__global__ void k_molptr(const int* __restrict__ batch) {
    int g = blockIdx.x * 256 + threadIdx.x;
    if (g > GG) return;
    if (g == GG) { g_molptr[GG] = NN; return; }
    int lo = 0, hi = NN;
    while (lo < hi) {
        int mid = (lo + hi) >> 1;
        if (batch[mid] < g) lo = mid + 1; else hi = mid;
    }
    g_molptr[g] = lo;
}

// ---------------- attention prep ----------------
__global__ void k_v2(const float* __restrict__ We, const float* __restrict__ atte) {
    int w = threadIdx.x >> 5, lane = threadIdx.x & 31;
    float s = 0.f;
    for (int k = lane; k < HH; k += 32) s += atte[k] * We[k * EDIM + w];
    s = warp_sum(s);
    if (lane == 0) {
        g_v[w] = s;
        if (w == 0) g_loopsum[0] = 0.f;
    }
}
__global__ void k_ae(const float* __restrict__ attr) {
    __shared__ float sv[EDIM];
    __shared__ float red[256];
    if (threadIdx.x < EDIM) sv[threadIdx.x] = g_v[threadIdx.x];
    __syncthreads();
    int e = blockIdx.x * 256 + threadIdx.x;
    float a = 0.f;
    if (e < EE) {
        const float* p = attr + (size_t)e * EDIM;
#pragma unroll
        for (int j = 0; j < EDIM; j++) a += p[j] * sv[j];
        g_ae[e] = a;
    }
    red[threadIdx.x] = a;
    __syncthreads();
    for (int st = 128; st; st >>= 1) {
        if (threadIdx.x < st) red[threadIdx.x] += red[threadIdx.x + st];
        __syncthreads();
    }
    if (threadIdx.x == 0) atomicAdd(g_loopsum, red[0]);
}

template <bool C0>
__global__ void k_edge_alpha(const int* __restrict__ src, const int* __restrict__ dst) {
    int e = blockIdx.x * 256 + threadIdx.x;
    if (e >= EE) return;
    float a = g_s[src[e]] + g_d[dst[e]];
    if (C0) a += g_ae[e];
    float sl = C0 ? 0.2f : 0.01f;
    a = a >= 0.f ? a : sl * a;
    g_ew[e] = expf(a);
}

template <bool C0>
__global__ void k_gather(const float* __restrict__ bias, __half* __restrict__ out3) {
    int d = (blockIdx.x * blockDim.x + threadIdx.x) >> 5;
    int lane = threadIdx.x & 31;
    if (d >= NN) return;
    int r0 = g_rowptr[d], r1 = g_rowptr[d + 1];
    float se = 0.f;
    for (int i = r0 + lane; i < r1; i += 32) se += g_ew[g_eid[i]];
    se = warp_sum(se);
    float wself = 0.f;
    if (C0) {
        float a = g_s[d] + g_d[d] + g_loopsum[0] * (1.0f / EE);
        a = a >= 0.f ? a : 0.2f * a;
        wself = expf(a);
        se += wself;
    }
    se = __shfl_sync(0xffffffffu, se, 0);
    float inv = 1.f / (se + 1e-16f);

    float4 a0 = make_float4(0.f, 0.f, 0.f, 0.f);
    float4 a1 = make_float4(0.f, 0.f, 0.f, 0.f);
    for (int i = r0; i < r1; i++) {
        int e = g_eid[i];
        int s = g_esrc[i];
        float w = g_ew[e];
        const float4* hs = (const float4*)(g_hW + (size_t)s * HH);
        float4 v = hs[lane];
        a0.x += w * v.x; a0.y += w * v.y; a0.z += w * v.z; a0.w += w * v.w;
        if (lane < 16) {
            float4 v2 = hs[lane + 32];
            a1.x += w * v2.x; a1.y += w * v2.y; a1.z += w * v2.z; a1.w += w * v2.w;
        }
    }
    if (C0) {
        const float4* hs = (const float4*)(g_hW + (size_t)d * HH);
        float4 v = hs[lane];
        a0.x += wself * v.x; a0.y += wself * v.y; a0.z += wself * v.z; a0.w += wself * v.w;
        if (lane < 16) {
            float4 v2 = hs[lane + 32];
            a1.x += wself * v2.x; a1.y += wself * v2.y; a1.z += wself * v2.z; a1.w += wself * v2.w;
        }
    }
    size_t rowb = (size_t)d * K2A;
    {
        int c0 = lane * 4;
        float x0 = a0.x * inv + bias[c0], x1 = a0.y * inv + bias[c0 + 1];
        float x2 = a0.z * inv + bias[c0 + 2], x3 = a0.w * inv + bias[c0 + 3];
        x0 = x0 > 0.f ? x0 : expm1f(x0); x1 = x1 > 0.f ? x1 : expm1f(x1);
        x2 = x2 > 0.f ? x2 : expm1f(x2); x3 = x3 > 0.f ? x3 : expm1f(x3);
        store_split4(out3 + rowb + c0, x0, x1, x2, x3);
    }
    if (lane < 16) {
        int c0 = 128 + lane * 4;
        float x0 = a1.x * inv + bias[c0], x1 = a1.y * inv + bias[c0 + 1];
        float x2 = a1.z * inv + bias[c0 + 2], x3 = a1.w * inv + bias[c0 + 3];
        x0 = x0 > 0.f ? x0 : expm1f(x0); x1 = x1 > 0.f ? x1 : expm1f(x1);
        x2 = x2 > 0.f ? x2 : expm1f(x2); x3 = x3 > 0.f ? x3 : expm1f(x3);
        store_split4(out3 + rowb + c0, x0, x1, x2, x3);
    }
}

// warp per graph: segment-sum pool + relu + split
__global__ void k_pool_seg() {
    int g = (blockIdx.x * blockDim.x + threadIdx.x) >> 5;
    int lane = threadIdx.x & 31;
    if (g >= GG) return;
    int p0 = g_molptr[g], p1 = g_molptr[g + 1];
    float4 a0 = make_float4(0.f, 0.f, 0.f, 0.f);
    float4 a1 = make_float4(0.f, 0.f, 0.f, 0.f);
    for (int i = p0; i < p1; i++) {
        const float4* xr = (const float4*)(g_x + (size_t)i * HH);
        float4 v = xr[lane];
        a0.x += v.x; a0.y += v.y; a0.z += v.z; a0.w += v.w;
        if (lane < 16) {
            float4 v2 = xr[lane + 32];
            a1.x += v2.x; a1.y += v2.y; a1.z += v2.z; a1.w += v2.w;
        }
    }
    a0.x = fmaxf(a0.x, 0.f); a0.y = fmaxf(a0.y, 0.f);
    a0.z = fmaxf(a0.z, 0.f); a0.w = fmaxf(a0.w, 0.f);
    size_t rowb = (size_t)g * K2A;
    ((float4*)(g_out + (size_t)g * HH))[lane] = a0;
    store_split4(g_a3m + rowb + lane * 4, a0.x, a0.y, a0.z, a0.w);
    if (lane < 16) {
        a1.x = fmaxf(a1.x, 0.f); a1.y = fmaxf(a1.y, 0.f);
        a1.z = fmaxf(a1.z, 0.f); a1.w = fmaxf(a1.w, 0.f);
        ((float4*)(g_out + (size_t)g * HH))[lane + 32] = a1;
        store_split4(g_a3m + rowb + 128 + lane * 4, a1.x, a1.y, a1.z, a1.w);
    }
}

// warp per graph: mol GAT gather + ELU + bias + split -> a3m2
__global__ void k_molgather(const float* __restrict__ mol_b) {
    int g = (blockIdx.x * blockDim.x + threadIdx.x) >> 5;
    int lane = threadIdx.x & 31;
    if (g >= GG) return;
    int p0 = g_molptr[g], p1 = g_molptr[g + 1];
    float dg = g_dmol[g];
    float se = 0.f;
    for (int i = p0 + lane; i < p1; i += 32) {
        float a = g_smol[i] + dg;
        a = a >= 0.f ? a : 0.01f * a;
        se += expf(a);
    }
    se = warp_sum(se);
    se = __shfl_sync(0xffffffffu, se, 0);
    float inv = 1.f / (se + 1e-16f);
    float4 a0 = make_float4(0.f, 0.f, 0.f, 0.f);
    float4 a1 = make_float4(0.f, 0.f, 0.f, 0.f);
    for (int i = p0; i < p1; i++) {
        float a = g_smol[i] + dg;
        a = a >= 0.f ? a : 0.01f * a;
        float w = expf(a);
        const float4* hs = (const float4*)(g_hW + (size_t)i * HH);
        float4 v = hs[lane];
        a0.x += w * v.x; a0.y += w * v.y; a0.z += w * v.z; a0.w += w * v.w;
        if (lane < 16) {
            float4 v2 = hs[lane + 32];
            a1.x += w * v2.x; a1.y += w * v2.y; a1.z += w * v2.z; a1.w += w * v2.w;
        }
    }
    size_t rowb = (size_t)g * K2A;
    {
        int c0 = lane * 4;
        float x0 = a0.x * inv + mol_b[c0], x1 = a0.y * inv + mol_b[c0 + 1];
        float x2 = a0.z * inv + mol_b[c0 + 2], x3 = a0.w * inv + mol_b[c0 + 3];
        x0 = x0 > 0.f ? x0 : expm1f(x0); x1 = x1 > 0.f ? x1 : expm1f(x1);
        x2 = x2 > 0.f ? x2 : expm1f(x2); x3 = x3 > 0.f ? x3 : expm1f(x3);
        store_split4(g_a3m2 + rowb + c0, x0, x1, x2, x3);
    }
    if (lane < 16) {
        int c0 = 128 + lane * 4;
        float x0 = a1.x * inv + mol_b[c0], x1 = a1.y * inv + mol_b[c0 + 1];
        float x2 = a1.z * inv + mol_b[c0 + 2], x3 = a1.w * inv + mol_b[c0 + 3];
        x0 = x0 > 0.f ? x0 : expm1f(x0); x1 = x1 > 0.f ? x1 : expm1f(x1);
        x2 = x2 > 0.f ? x2 : expm1f(x2); x3 = x3 > 0.f ? x3 : expm1f(x3);
        store_split4(g_a3m2 + rowb + c0, x0, x1, x2, x3);
    }
}

__global__ void k_final(const float* __restrict__ W, const float* __restrict__ b,
                        float* __restrict__ out) {
    int gw = (blockIdx.x * blockDim.x + threadIdx.x) >> 5;
    int lane = threadIdx.x & 31;
    if (gw >= GG) return;
    float s = 0.f;
    for (int k = lane; k < HH; k += 32) s += g_out[gw * HH + k] * W[k];
    s = warp_sum(s);
    if (lane == 0) out[gw] = s + b[0];
}

// ---------------- host ----------------
static inline int cdiv(int a, int b) { return (a + b - 1) / b; }

extern "C" void kernel_launch(void* const* d_in, const int* in_sizes, int n_in,
                              void* d_out, int out_size) {
    const float* x_in = (const float*)d_in[0];
    const int* eidx = (const int*)d_in[1];
    const float* eattr = (const float*)d_in[2];
    const int* batch = (const int*)d_in[3];
    const float* lin1_W = (const float*)d_in[4];
    const float* lin1_b = (const float*)d_in[5];
    const float* conv0_W = (const float*)d_in[6];
    const float* conv0_att_s = (const float*)d_in[7];
    const float* conv0_att_d = (const float*)d_in[8];
    const float* conv0_We = (const float*)d_in[9];
    const float* conv0_att_e = (const float*)d_in[10];
    const float* conv0_b = (const float*)d_in[11];
    const float* convs_W = (const float*)d_in[12];
    const float* convs_att_s = (const float*)d_in[13];
    const float* convs_att_d = (const float*)d_in[14];
    const float* convs_b = (const float*)d_in[15];
    const float* gru_Wih = (const float*)d_in[16];
    const float* gru_Whh = (const float*)d_in[17];
    const float* gru_bih = (const float*)d_in[18];
    const float* gru_bhh = (const float*)d_in[19];
    const float* mol_Wsrc = (const float*)d_in[20];
    const float* mol_Wdst = (const float*)d_in[21];
    const float* mol_att_s = (const float*)d_in[22];
    const float* mol_att_d = (const float*)d_in[23];
    const float* mol_b = (const float*)d_in[24];
    const float* mgru_Wih = (const float*)d_in[25];
    const float* mgru_Whh = (const float*)d_in[26];
    const float* mgru_bih = (const float*)d_in[27];
    const float* mgru_bhh = (const float*)d_in[28];
    const float* lin2_W = (const float*)d_in[29];
    const float* lin2_b = (const float*)d_in[30];

    const int* src = eidx;
    const int* dst = eidx + EE;

    float *px, *phW, *pgh, *ps, *pd, *pout, *psmol, *pdmol;
    float *bp_ih, *bp_hh, *bp_mi, *bp_mh;
    int* pdeg;
    cudaGetSymbolAddress((void**)&px, g_x);
    cudaGetSymbolAddress((void**)&phW, g_hW);
    cudaGetSymbolAddress((void**)&pgh, g_gh);
    cudaGetSymbolAddress((void**)&ps, g_s);
    cudaGetSymbolAddress((void**)&pd, g_d);
    cudaGetSymbolAddress((void**)&pout, g_out);
    cudaGetSymbolAddress((void**)&psmol, g_smol);
    cudaGetSymbolAddress((void**)&pdmol, g_dmol);
    cudaGetSymbolAddress((void**)&pdeg, g_deg);
    cudaGetSymbolAddress((void**)&bp_ih, g_bp_ih);
    cudaGetSymbolAddress((void**)&bp_hh, g_bp_hh);
    cudaGetSymbolAddress((void**)&bp_mi, g_bp_mi);
    cudaGetSymbolAddress((void**)&bp_mh, g_bp_mh);
    __half *a3, *a3b, *b3, *b3wd, *b3wi, *b3wh, *a3m, *a3m2;
    cudaGetSymbolAddress((void**)&a3, g_a3);
    cudaGetSymbolAddress((void**)&a3b, g_a3b);
    cudaGetSymbolAddress((void**)&b3, g_b3);
    cudaGetSymbolAddress((void**)&b3wd, g_b3wd);
    cudaGetSymbolAddress((void**)&b3wi, g_b3wi);
    cudaGetSymbolAddress((void**)&b3wh, g_b3wh);
    cudaGetSymbolAddress((void**)&a3m, g_a3m);
    cudaGetSymbolAddress((void**)&a3m2, g_a3m2);

    cudaFuncSetAttribute(bgemm<1, false, false, false>, cudaFuncAttributeMaxDynamicSharedMemorySize, BG_SMEM);
    cudaFuncSetAttribute(bgemm<2, true, false, false>, cudaFuncAttributeMaxDynamicSharedMemorySize, BG_SMEM);
    cudaFuncSetAttribute(bgemm<0, false, true, false>, cudaFuncAttributeMaxDynamicSharedMemorySize, BG_SMEM);
    cudaFuncSetAttribute(bgemm<0, false, false, true>, cudaFuncAttributeMaxDynamicSharedMemorySize, BG_SMEM);

    cudaStream_t s2;
    cudaStreamCreate(&s2);
    cudaEvent_t ev[32];
    for (int i = 0; i < 32; i++) cudaEventCreateWithFlags(&ev[i], cudaEventDisableTiming);
#define REC0(i) cudaEventRecord(ev[i], 0)
#define RECS(i) cudaEventRecord(ev[i], s2)
#define W0(i) cudaStreamWaitEvent(0, ev[i], 0)
#define WS(i) cudaStreamWaitEvent(s2, ev[i], 0)

    auto bg1 = [&](const __half* A, const __half* B, const float* bias,
                   float* C, int M, int Nc, int K3, cudaStream_t st) {
        bgemm<1, false, false, false><<<dim3(Nc / BN, cdiv(M, 128)), 256, BG_SMEM, st>>>(
            A, B, bias, C, nullptr, nullptr, nullptr, nullptr, nullptr, nullptr, nullptr, M, Nc, K3);
    };
    auto bgD = [&](const __half* A, const __half* B, float* C,
                   const float* u, const float* w, float* ou, float* ow,
                   int M, int Nc, int K3) {
        bgemm<0, false, true, false><<<dim3(Nc / BN, cdiv(M, 128)), 256, BG_SMEM>>>(
            A, B, nullptr, C, nullptr, u, w, ou, ow, nullptr, nullptr, M, Nc, K3);
    };
    auto bgGRU = [&](const __half* A, const __half* B, const float* bias_p,
                     const float* ghp, float* xb, __half* out3, int M) {
        bgemm<0, false, false, true><<<dim3(H3 / BN, cdiv(M, 128)), 256, BG_SMEM>>>(
            A, B, bias_p, nullptr, out3, nullptr, nullptr, nullptr, nullptr, ghp, xb, M, H3, K2A);
    };

    // ---- main prologue (slot 3 = bgD profiled) ----
    REC0(0);
    k_splitA<<<cdiv(NN * CC, 256), 256>>>(x_in, a3b);
    k_splitB2<<<cdiv(HH * CC + HH * HH, 256), 256>>>(lin1_W, b3wd, conv0_W, b3);
    bgemm<2, true, false, false><<<dim3(HH / BN, cdiv(NN, 128)), 256, BG_SMEM>>>(
        a3b, b3wd, lin1_b, px, a3, nullptr, nullptr, nullptr, nullptr, nullptr, nullptr,
        NN, HH, 2 * CC);
    REC0(1);  // a3 ready
    bgD(a3, b3, phW, conv0_att_s, conv0_att_d, ps, pd, NN, HH, K2A);  // PROFILED

    // ---- s2: ae + CSR + conv0 gh chain ----
    WS(0);
    k_v2<<<1, 512, 0, s2>>>(conv0_We, conv0_att_e);
    k_ae<<<cdiv(EE, 256), 256, 0, s2>>>(eattr);
    RECS(2);  // ae ready
    k_zero_int<<<cdiv(NN, 256), 256, 0, s2>>>(pdeg, NN);
    k_hist<<<cdiv(EE, 256), 256, 0, s2>>>(dst);
    k_scan_block<<<NSCAN, SCAN_BLK, 0, s2>>>();
    k_scan_mid<<<1, 32, 0, s2>>>();
    k_scan_add<<<cdiv(NN + 1, 256), 256, 0, s2>>>();
    k_fill<<<cdiv(EE, 256), 256, 0, s2>>>(dst, src);
    k_molptr<<<cdiv(GG + 1, 256), 256, 0, s2>>>(batch);
    RECS(3);  // CSR ready
    WS(1);
    k_splitB_perm<<<cdiv(H3 * HH, 256), 256, 0, s2>>>(gru_Whh, b3wh);
    k_permbias<<<1, H3, 0, s2>>>(gru_bhh, bp_hh, gru_bih, bp_ih);
    bg1(a3, b3wh, bp_hh, pgh, NN, H3, K2A, s2);
    RECS(4);  // gh ready

    // ---- conv0 main chain ----
    W0(2);
    k_edge_alpha<true><<<cdiv(EE, 256), 256>>>(src, dst);
    W0(3);
    k_splitB_perm<<<cdiv(H3 * HH, 256), 256>>>(gru_Wih, b3wi);
    k_gather<true><<<cdiv(NN * 32, 256), 256>>>(conv0_b, a3b);
    W0(4);
    bgGRU(a3b, b3wi, bp_ih, pgh, px, a3, NN);
    REC0(5);

    // ---- remaining atom conv layers ----
    for (int l = 0; l < 2; l++) {
        WS(5 + 2 * l);
        k_splitB_perm<<<cdiv(H3 * HH, 256), 256, 0, s2>>>(gru_Whh + (size_t)(l + 1) * H3 * HH, b3wh);
        k_permbias<<<1, H3, 0, s2>>>(gru_bhh + (l + 1) * H3, bp_hh, gru_bih + (l + 1) * H3, bp_ih);
        bg1(a3, b3wh, bp_hh, pgh, NN, H3, K2A, s2);
        RECS(6 + 2 * l);
        k_splitB<<<cdiv(HH * HH, 256), 256>>>(convs_W + (size_t)l * HH * HH, b3, HH, HH);
        k_zero2<<<cdiv(NN, 256), 256>>>(ps, pd, NN, NN);
        bgD(a3, b3, phW, convs_att_s + l * HH, convs_att_d + l * HH, ps, pd, NN, HH, K2A);
        k_edge_alpha<false><<<cdiv(EE, 256), 256>>>(src, dst);
        k_splitB_perm<<<cdiv(H3 * HH, 256), 256>>>(gru_Wih + (size_t)(l + 1) * H3 * HH, b3wi);
        k_gather<false><<<cdiv(NN * 32, 256), 256>>>(convs_b + l * HH, a3b);
        W0(6 + 2 * l);
        bgGRU(a3b, b3wi, bp_ih, pgh, px, a3, NN);
        REC0(7 + 2 * l);  // 7, 9
    }

    // ---- molecule readout ----
    WS(9);
    k_pool_seg<<<cdiv(GG * 32, 256), 256, 0, s2>>>();
    k_splitB<<<cdiv(HH * HH, 256), 256, 0, s2>>>(mol_Wdst, b3wd, HH, HH);
    k_splitB_perm<<<cdiv(H3 * HH, 256), 256, 0, s2>>>(mgru_Wih, b3wi);
    k_splitB_perm<<<cdiv(H3 * HH, 256), 256, 0, s2>>>(mgru_Whh, b3wh);
    k_permbias<<<1, H3, 0, s2>>>(mgru_bih, bp_mi, mgru_bhh, bp_mh);
    RECS(10);
    k_splitB<<<cdiv(HH * HH, 256), 256>>>(mol_Wsrc, b3, HH, HH);
    k_zero2<<<cdiv(NN, 256), 256>>>(psmol, psmol, NN, 0);
    bgD(a3, b3, phW, mol_att_s, nullptr, psmol, nullptr, NN, HH, K2A);
    W0(10);

    for (int t = 0; t < 2; t++) {
        REC0(11 + 2 * t);
        WS(11 + 2 * t);
        bg1(a3m, b3wh, bp_mh, pgh, GG, H3, K2A, s2);
        RECS(12 + 2 * t);
        k_zero2<<<cdiv(GG, 256), 256>>>(pdmol, pdmol, GG, 0);
        bgD(a3m, b3wd, nullptr, mol_att_d, nullptr, pdmol, nullptr, GG, HH, K2A);
        k_molgather<<<cdiv(GG * 32, 256), 256>>>(mol_b);
        W0(12 + 2 * t);
        bgGRU(a3m2, b3wi, bp_mi, pgh, pout, a3m, GG);
    }

    k_final<<<cdiv(GG * 32, 256), 256>>>(lin2_W, lin2_b, (float*)d_out);
#undef REC0
#undef RECS
#undef W0
#undef WS
}

// round 15
// speedup vs baseline: 1.2014x; 1.0001x over previous
#include <cuda_runtime.h>
#include <cuda_fp16.h>
#include <math.h>
#include <stdint.h>

#define NN 50000
#define EE 800000
#define CC 64
#define HH 192
#define H3 576
#define EDIM 16
#define GG 2048
#define K2A (2 * HH)  // 384: fp16x2 K for H-sized GEMMs

// ---------------- scratch ----------------
__device__ __align__(16) float g_x[NN * HH];
__device__ __align__(16) __half g_hWh[NN * HH];   // fp16 hW (gather input)
__device__ __align__(16) float g_gh[NN * H3];
__device__ float g_s[NN];
__device__ float g_d[NN];
__device__ float g_ae[EE];
__device__ float g_ew[EE];
__device__ float g_v[EDIM];
__device__ float g_loopsum[1];
__device__ __align__(16) float g_out[GG * HH];
__device__ float g_smol[NN];
__device__ float g_dmol[GG];
__device__ float g_bp_ih[H3];
__device__ float g_bp_hh[H3];
__device__ float g_bp_mi[H3];
__device__ float g_bp_mh[H3];
// CSR
__device__ int g_deg[NN];
__device__ int g_cursor[NN];
__device__ int g_rowptr[NN + 1];
__device__ int g_eid[EE];
__device__ int g_esrc[EE];
__device__ int g_bsums[64];
__device__ int g_molptr[GG + 1];
// fp16x2 split buffers (A-mode: [hi|lo] exact; B-mode: [hi|hi])
__device__ __align__(16) __half g_a3[(size_t)NN * K2A];
__device__ __align__(16) __half g_a3b[(size_t)NN * K2A];
__device__ __align__(16) __half g_b3[(size_t)HH * K2A];
__device__ __align__(16) __half g_b3wd[(size_t)HH * K2A];
__device__ __align__(16) __half g_b3wi[(size_t)H3 * K2A];
__device__ __align__(16) __half g_b3wh[(size_t)H3 * K2A];
__device__ __align__(16) __half g_a3m[(size_t)GG * K2A];
__device__ __align__(16) __half g_a3m2[(size_t)GG * K2A];

// ---------------- helpers ----------------
__device__ __forceinline__ float warp_sum(float v) {
#pragma unroll
    for (int o = 16; o; o >>= 1) v += __shfl_down_sync(0xffffffffu, v, o);
    return v;
}
__device__ __forceinline__ float sigm(float x) { return 1.f / (1.f + expf(-x)); }
__device__ __forceinline__ uint32_t smem_u32(const void* p) {
    uint32_t a;
    asm("{ .reg .u64 t; cvta.to.shared.u64 t, %1; cvt.u32.u64 %0, t; }" : "=r"(a) : "l"(p));
    return a;
}
__device__ __forceinline__ void cp16(uint32_t s, const void* g) {
    asm volatile("cp.async.cg.shared.global [%0], [%1], 16;" :: "r"(s), "l"(g));
}
__device__ __forceinline__ void ldsm4(uint32_t& r0, uint32_t& r1, uint32_t& r2, uint32_t& r3,
                                      uint32_t addr) {
    asm volatile("ldmatrix.sync.aligned.m8n8.x4.shared.b16 {%0,%1,%2,%3}, [%4];"
                 : "=r"(r0), "=r"(r1), "=r"(r2), "=r"(r3) : "r"(addr));
}
__device__ __forceinline__ void mma16816(float* d, const uint32_t* a, const uint32_t* b) {
    asm volatile(
        "mma.sync.aligned.m16n8k16.row.col.f32.f16.f16.f32 "
        "{%0,%1,%2,%3}, {%4,%5,%6,%7}, {%8,%9}, {%0,%1,%2,%3};"
        : "+f"(d[0]), "+f"(d[1]), "+f"(d[2]), "+f"(d[3])
        : "r"(a[0]), "r"(a[1]), "r"(a[2]), "r"(a[3]), "r"(b[0]), "r"(b[1]));
}
__device__ __forceinline__ void redf(float* p, float v) {
    asm volatile("red.global.add.f32 [%0], %1;" :: "l"(p), "f"(v) : "memory");
}
__device__ __forceinline__ unsigned short hb(__half h) {
    return *reinterpret_cast<unsigned short*>(&h);
}
// A-mode fp16x2 store: hi (4 vals) at [0], lo at [+HH]
__device__ __forceinline__ void store_split4(__half* base, float v0, float v1,
                                             float v2, float v3) {
    __half h0 = __float2half_rn(v0), h1 = __float2half_rn(v1);
    __half h2 = __float2half_rn(v2), h3 = __float2half_rn(v3);
    __half l0 = __float2half_rn(v0 - __half2float(h0));
    __half l1 = __float2half_rn(v1 - __half2float(h1));
    __half l2 = __float2half_rn(v2 - __half2float(h2));
    __half l3 = __float2half_rn(v3 - __half2float(h3));
    uint2 hp, lp;
    hp.x = ((uint32_t)hb(h1) << 16) | hb(h0);
    hp.y = ((uint32_t)hb(h3) << 16) | hb(h2);
    lp.x = ((uint32_t)hb(l1) << 16) | hb(l0);
    lp.y = ((uint32_t)hb(l3) << 16) | hb(l2);
    *(uint2*)(base) = hp;
    *(uint2*)(base + HH) = lp;
}
// load 4 halves -> 4 floats
__device__ __forceinline__ void ldh4(const __half* p, float& f0, float& f1, float& f2, float& f3) {
    uint2 raw = *(const uint2*)p;
    __half2 a = *reinterpret_cast<__half2*>(&raw.x);
    __half2 b = *reinterpret_cast<__half2*>(&raw.y);
    float2 fa = __half22float2(a), fb = __half22float2(b);
    f0 = fa.x; f1 = fa.y; f2 = fb.x; f3 = fb.y;
}

// ===== fp16 mma.sync NT GEMM: 128x96 tile, 256 threads, 2 CTAs/SM, 3-stage pipeline =====
// DOT path writes half output to C3 (row-major Nc) and fused rowdots to ou/ow.
#define BN 96
#define A_BUF 16384
#define B_BUF 12288
#define BG_SMEM (3 * A_BUF + 3 * B_BUF)
template <int EPI, bool SPLIT, bool DOT, bool GRUF>
__global__ void __launch_bounds__(256, 2)
bgemm(const __half* __restrict__ A3, const __half* __restrict__ B3,
      const float* __restrict__ bias, float* __restrict__ C,
      __half* __restrict__ C3,
      const float* __restrict__ u, const float* __restrict__ w,
      float* __restrict__ ou, float* __restrict__ ow,
      const float* __restrict__ gh, float* __restrict__ xb,
      int M, int Nc, int K3) {
    extern __shared__ __align__(16) char dsm[];
    const int tid = threadIdx.x;
    const int lane = tid & 31, wid = tid >> 5;
    const int wm = wid & 3, wn = wid >> 2;
    const int row0 = blockIdx.y * 128, col0 = blockIdx.x * BN;
    const uint32_t aB = smem_u32(dsm);
    const uint32_t bB = aB + 3 * A_BUF;

    float acc[2][6][4] = {};
    const int nc = K3 >> 6;

    auto issue = [&](int c, int buf) {
        const uint32_t ab = aB + buf * A_BUF;
        const uint32_t bb = bB + buf * B_BUF;
#pragma unroll
        for (int q = 0; q < 4; q++) {
            int idx = q * 256 + tid;
            int r = idx >> 3, kc = idx & 7;
            int grow = row0 + r;
            grow = grow < M ? grow : M - 1;
            cp16(ab + (uint32_t)(r * 128 + ((kc * 16) ^ ((r & 7) << 4))),
                 A3 + (size_t)grow * K3 + c * 64 + kc * 8);
        }
#pragma unroll
        for (int q = 0; q < 3; q++) {
            int idx = q * 256 + tid;
            int r = idx >> 3, kc = idx & 7;
            cp16(bb + (uint32_t)(r * 128 + ((kc * 16) ^ ((r & 7) << 4))),
                 B3 + (size_t)(col0 + r) * K3 + c * 64 + kc * 8);
        }
        asm volatile("cp.async.commit_group;" ::: "memory");
    };

    const int a_r = wm * 32 + ((lane >> 3) & 1) * 8 + (lane & 7);
    const int a_kb = ((lane >> 4) & 1) * 16;
    const int b_r = wn * 48 + ((lane >> 4) & 1) * 8 + (lane & 7);
    const int b_kb = ((lane >> 3) & 1) * 16;

    issue(0, 0);
    issue(1, 1);
    for (int c = 0; c < nc; c++) {
        const int buf = c % 3;
        if (c + 2 < nc) {
            issue(c + 2, (c + 2) % 3);
            asm volatile("cp.async.wait_group 2;" ::: "memory");
        } else if (c + 1 < nc) {
            asm volatile("cp.async.wait_group 1;" ::: "memory");
        } else {
            asm volatile("cp.async.wait_group 0;" ::: "memory");
        }
        __syncthreads();
        const uint32_t ab = aB + buf * A_BUF;
        const uint32_t bb = bB + buf * B_BUF;
#pragma unroll
        for (int ks = 0; ks < 4; ks++) {
            uint32_t af[2][4], bfr[3][4];
#pragma unroll
            for (int mi = 0; mi < 2; mi++) {
                int r = a_r + mi * 16;
                ldsm4(af[mi][0], af[mi][1], af[mi][2], af[mi][3],
                      ab + (uint32_t)(r * 128 + ((ks * 32 + a_kb) ^ ((r & 7) << 4))));
            }
#pragma unroll
            for (int p = 0; p < 3; p++) {
                int r = b_r + p * 16;
                ldsm4(bfr[p][0], bfr[p][1], bfr[p][2], bfr[p][3],
                      bb + (uint32_t)(r * 128 + ((ks * 32 + b_kb) ^ ((r & 7) << 4))));
            }
#pragma unroll
            for (int mi = 0; mi < 2; mi++)
#pragma unroll
                for (int ni = 0; ni < 6; ni++) {
                    uint32_t b2[2] = {bfr[ni >> 1][(ni & 1) * 2], bfr[ni >> 1][(ni & 1) * 2 + 1]};
                    mma16816(acc[mi][ni], af[mi], b2);
                }
        }
        __syncthreads();
    }

    const int qr = lane >> 2, qc = (lane & 3) * 2;

    if (GRUF) {
        float* S = (float*)dsm;
        const int ST = 100;
        const int r_l = tid >> 3;
        const int f0 = (tid & 7) * 4;
#pragma unroll
        for (int mi = 0; mi < 2; mi++) {
#pragma unroll
            for (int half = 0; half < 2; half++) {
#pragma unroll
                for (int ni = 0; ni < 6; ni++) {
                    int cl = wn * 48 + ni * 8 + qc;
                    float v0 = acc[mi][ni][half * 2 + 0] + bias[col0 + cl];
                    float v1 = acc[mi][ni][half * 2 + 1] + bias[col0 + cl + 1];
                    *(float2*)&S[(wm * 8 + qr) * ST + cl] = make_float2(v0, v1);
                }
                __syncthreads();
                int row = row0 + (r_l >> 3) * 32 + mi * 16 + half * 8 + (r_l & 7);
                if (row < M) {
                    const float* Sr = &S[r_l * ST + 3 * f0];
                    const float* ghr = gh + (size_t)row * Nc + col0 + 3 * f0;
                    int fg = col0 / 3 + f0;
                    float4 xv = *(const float4*)(xb + (size_t)row * HH + fg);
                    float xo[4] = {xv.x, xv.y, xv.z, xv.w};
                    float o[4];
#pragma unroll
                    for (int q = 0; q < 4; q++) {
                        float gir = Sr[3 * q], giz = Sr[3 * q + 1], gin = Sr[3 * q + 2];
                        float hr = ghr[3 * q], hz = ghr[3 * q + 1], hn = ghr[3 * q + 2];
                        float r = sigm(gir + hr);
                        float z = sigm(giz + hz);
                        float n = tanhf(gin + r * hn);
                        float v = (1.f - z) * n + z * xo[q];
                        o[q] = v > 0.f ? v : 0.f;
                    }
                    *(float4*)(xb + (size_t)row * HH + fg) = make_float4(o[0], o[1], o[2], o[3]);
                    store_split4(C3 + (size_t)row * K2A + fg, o[0], o[1], o[2], o[3]);
                }
                __syncthreads();
            }
        }
        return;
    }

#pragma unroll
    for (int mi = 0; mi < 2; mi++) {
#pragma unroll
        for (int half = 0; half < 2; half++) {
            int row = row0 + wm * 32 + mi * 16 + half * 8 + qr;
            bool ok = row < M;
            float p_s = 0.f, p_d = 0.f;
#pragma unroll
            for (int ni = 0; ni < 6; ni++) {
                int cc0 = col0 + wn * 48 + ni * 8 + qc;
                float v0 = acc[mi][ni][half * 2 + 0];
                float v1 = acc[mi][ni][half * 2 + 1];
                if (EPI >= 1) { v0 += bias[cc0]; v1 += bias[cc0 + 1]; }
                if (EPI == 2) {
                    v0 = v0 > 0.f ? v0 : 0.01f * v0;
                    v1 = v1 > 0.f ? v1 : 0.01f * v1;
                }
                if (DOT) {
                    p_s += v0 * u[cc0] + v1 * u[cc0 + 1];
                    if (w) p_d += v0 * w[cc0] + v1 * w[cc0 + 1];
                    if (ok && C3) {  // half output (hW)
                        __half2 hv = __floats2half2_rn(v0, v1);
                        *(__half2*)(C3 + (size_t)row * Nc + cc0) = hv;
                    }
                } else {
                    if (ok && C) *(float2*)(C + (size_t)row * Nc + cc0) = make_float2(v0, v1);
                }
                if (SPLIT && ok) {
                    size_t base = (size_t)row * (2 * Nc) + cc0;
                    __half h0 = __float2half_rn(v0);
                    __half l0 = __float2half_rn(v0 - __half2float(h0));
                    __half h1 = __float2half_rn(v1);
                    __half l1 = __float2half_rn(v1 - __half2float(h1));
                    C3[base] = h0; C3[base + 1] = h1;
                    C3[base + Nc] = l0; C3[base + Nc + 1] = l1;
                }
            }
            if (DOT) {
                p_s += __shfl_xor_sync(0xffffffffu, p_s, 1);
                p_s += __shfl_xor_sync(0xffffffffu, p_s, 2);
                if (w) {
                    p_d += __shfl_xor_sync(0xffffffffu, p_d, 1);
                    p_d += __shfl_xor_sync(0xffffffffu, p_d, 2);
                }
                if (ok && (lane & 3) == 0) {
                    redf(ou + row, p_s);
                    if (w) redf(ow + row, p_d);
                }
            }
        }
    }
}

// ---------------- split kernels ----------------
__global__ void k_splitA(const float* __restrict__ X, __half* __restrict__ Y) {
    int idx = blockIdx.x * 256 + threadIdx.x;
    if (idx < NN) { g_s[idx] = 0.f; g_d[idx] = 0.f; }
    if (idx >= NN * CC) return;
    int r = idx / CC, j = idx % CC;
    float v = X[idx];
    __half hi = __float2half_rn(v);
    __half lo = __float2half_rn(v - __half2float(hi));
    size_t b = (size_t)r * 2 * CC + j;
    Y[b] = hi; Y[b + CC] = lo;
}
__global__ void k_splitB(const float* __restrict__ X, __half* __restrict__ Y,
                         int rows, int K) {
    int idx = blockIdx.x * 256 + threadIdx.x;
    if (idx >= rows * K) return;
    int r = idx / K, j = idx % K;
    __half hi = __float2half_rn(X[idx]);
    size_t b = (size_t)r * 2 * K + j;
    Y[b] = hi; Y[b + K] = hi;
}
__global__ void k_splitB2(const float* __restrict__ X1, __half* __restrict__ Y1,
                          const float* __restrict__ X2, __half* __restrict__ Y2) {
    int idx = blockIdx.x * 256 + threadIdx.x;
    const int n1 = HH * CC;
    if (idx < n1) {
        int r = idx / CC, j = idx % CC;
        __half hi = __float2half_rn(X1[idx]);
        size_t b = (size_t)r * 2 * CC + j;
        Y1[b] = hi; Y1[b + CC] = hi;
    }
    int i2 = idx - n1;
    if (i2 >= 0 && i2 < HH * HH) {
        int r = i2 / HH, j = i2 % HH;
        __half hi = __float2half_rn(X2[i2]);
        size_t b = (size_t)r * 2 * HH + j;
        Y2[b] = hi; Y2[b + HH] = hi;
    }
}
__global__ void k_splitB_perm(const float* __restrict__ X, __half* __restrict__ Y) {
    int idx = blockIdx.x * 256 + threadIdx.x;
    if (idx >= H3 * HH) return;
    int j = idx / HH, k = idx % HH;
    int g = j / HH, f = j % HH;
    int rp = 3 * f + g;
    __half hi = __float2half_rn(X[idx]);
    size_t b = (size_t)rp * K2A + k;
    Y[b] = hi; Y[b + HH] = hi;
}
__global__ void k_permbias(const float* __restrict__ b1, float* __restrict__ o1,
                           const float* __restrict__ b2, float* __restrict__ o2) {
    int j = threadIdx.x;
    int g = j / HH, f = j % HH;
    o1[3 * f + g] = b1[j];
    o2[3 * f + g] = b2[j];
}

// ---------------- CSR build ----------------
__global__ void k_zero_int(int* p, int n) {
    int i = blockIdx.x * 256 + threadIdx.x;
    if (i < n) p[i] = 0;
}
__global__ void k_zero2(float* a, float* b, int na, int nb) {
    int i = blockIdx.x * 256 + threadIdx.x;
    if (i < na) a[i] = 0.f;
    if (i < nb) b[i] = 0.f;
}
__global__ void k_hist(const int* __restrict__ dst) {
    int e = blockIdx.x * 256 + threadIdx.x;
    if (e < EE) atomicAdd(&g_deg[dst[e]], 1);
}
#define SCAN_BLK 1024
#define NSCAN 49
__global__ void k_scan_block() {
    __shared__ int s[SCAN_BLK];
    int b = blockIdx.x, t = threadIdx.x;
    int i = b * SCAN_BLK + t;
    int v = (i < NN) ? g_deg[i] : 0;
    s[t] = v;
    __syncthreads();
    for (int off = 1; off < SCAN_BLK; off <<= 1) {
        int x = (t >= off) ? s[t - off] : 0;
        __syncthreads();
        s[t] += x;
        __syncthreads();
    }
    if (i < NN) g_rowptr[i] = s[t] - v;
    if (t == SCAN_BLK - 1) g_bsums[b] = s[t];
}
__global__ void k_scan_mid() {
    if (threadIdx.x == 0) {
        int acc = 0;
        for (int b = 0; b < NSCAN; b++) {
            int x = g_bsums[b];
            g_bsums[b] = acc;
            acc += x;
        }
    }
}
__global__ void k_scan_add() {
    int i = blockIdx.x * 256 + threadIdx.x;
    if (i < NN) {
        int v = g_rowptr[i] + g_bsums[i >> 10];
        g_rowptr[i] = v;
        g_cursor[i] = v;
    }
    if (i == NN) g_rowptr[NN] = EE;
}
__global__ void k_fill(const int* __restrict__ dst, const int* __restrict__ src) {
    int e = blockIdx.x * 256 + threadIdx.x;
    if (e >= EE) return;
    int pos = atomicAdd(&g_cursor[dst[e]], 1);
    g_eid[pos] = e;
    g_esrc[pos] = src[e];
}
__global__ void k_molptr(const int* __restrict__ batch) {
    int g = blockIdx.x * 256 + threadIdx.x;
    if (g > GG) return;
    if (g == GG) { g_molptr[GG] = NN; return; }
    int lo = 0, hi = NN;
    while (lo < hi) {
        int mid = (lo + hi) >> 1;
        if (batch[mid] < g) lo = mid + 1; else hi = mid;
    }
    g_molptr[g] = lo;
}

// ---------------- attention prep ----------------
__global__ void k_v2(const float* __restrict__ We, const float* __restrict__ atte) {
    int w = threadIdx.x >> 5, lane = threadIdx.x & 31;
    float s = 0.f;
    for (int k = lane; k < HH; k += 32) s += atte[k] * We[k * EDIM + w];
    s = warp_sum(s);
    if (lane == 0) {
        g_v[w] = s;
        if (w == 0) g_loopsum[0] = 0.f;
    }
}
__global__ void k_ae(const float* __restrict__ attr) {
    __shared__ float sv[EDIM];
    __shared__ float red[256];
    if (threadIdx.x < EDIM) sv[threadIdx.x] = g_v[threadIdx.x];
    __syncthreads();
    int e = blockIdx.x * 256 + threadIdx.x;
    float a = 0.f;
    if (e < EE) {
        const float* p = attr + (size_t)e * EDIM;
#pragma unroll
        for (int j = 0; j < EDIM; j++) a += p[j] * sv[j];
        g_ae[e] = a;
    }
    red[threadIdx.x] = a;
    __syncthreads();
    for (int st = 128; st; st >>= 1) {
        if (threadIdx.x < st) red[threadIdx.x] += red[threadIdx.x + st];
        __syncthreads();
    }
    if (threadIdx.x == 0) atomicAdd(g_loopsum, red[0]);
}

template <bool C0>
__global__ void k_edge_alpha(const int* __restrict__ src, const int* __restrict__ dst) {
    int e = blockIdx.x * 256 + threadIdx.x;
    if (e >= EE) return;
    float a = g_s[src[e]] + g_d[dst[e]];
    if (C0) a += g_ae[e];
    float sl = C0 ? 0.2f : 0.01f;
    a = a >= 0.f ? a : sl * a;
    g_ew[e] = expf(a);
}

template <bool C0>
__global__ void k_gather(const float* __restrict__ bias, __half* __restrict__ out3) {
    int d = (blockIdx.x * blockDim.x + threadIdx.x) >> 5;
    int lane = threadIdx.x & 31;
    if (d >= NN) return;
    int r0 = g_rowptr[d], r1 = g_rowptr[d + 1];
    float se = 0.f;
    for (int i = r0 + lane; i < r1; i += 32) se += g_ew[g_eid[i]];
    se = warp_sum(se);
    float wself = 0.f;
    if (C0) {
        float a = g_s[d] + g_d[d] + g_loopsum[0] * (1.0f / EE);
        a = a >= 0.f ? a : 0.2f * a;
        wself = expf(a);
        se += wself;
    }
    se = __shfl_sync(0xffffffffu, se, 0);
    float inv = 1.f / (se + 1e-16f);

    float4 a0 = make_float4(0.f, 0.f, 0.f, 0.f);
    float4 a1 = make_float4(0.f, 0.f, 0.f, 0.f);
    for (int i = r0; i < r1; i++) {
        int e = g_eid[i];
        int s = g_esrc[i];
        float w = g_ew[e];
        const __half* hs = g_hWh + (size_t)s * HH;
        float f0, f1, f2, f3;
        ldh4(hs + lane * 4, f0, f1, f2, f3);
        a0.x += w * f0; a0.y += w * f1; a0.z += w * f2; a0.w += w * f3;
        if (lane < 16) {
            ldh4(hs + 128 + lane * 4, f0, f1, f2, f3);
            a1.x += w * f0; a1.y += w * f1; a1.z += w * f2; a1.w += w * f3;
        }
    }
    if (C0) {
        const __half* hs = g_hWh + (size_t)d * HH;
        float f0, f1, f2, f3;
        ldh4(hs + lane * 4, f0, f1, f2, f3);
        a0.x += wself * f0; a0.y += wself * f1; a0.z += wself * f2; a0.w += wself * f3;
        if (lane < 16) {
            ldh4(hs + 128 + lane * 4, f0, f1, f2, f3);
            a1.x += wself * f0; a1.y += wself * f1; a1.z += wself * f2; a1.w += wself * f3;
        }
    }
    size_t rowb = (size_t)d * K2A;
    {
        int c0 = lane * 4;
        float x0 = a0.x * inv + bias[c0], x1 = a0.y * inv + bias[c0 + 1];
        float x2 = a0.z * inv + bias[c0 + 2], x3 = a0.w * inv + bias[c0 + 3];
        x0 = x0 > 0.f ? x0 : expm1f(x0); x1 = x1 > 0.f ? x1 : expm1f(x1);
        x2 = x2 > 0.f ? x2 : expm1f(x2); x3 = x3 > 0.f ? x3 : expm1f(x3);
        store_split4(out3 + rowb + c0, x0, x1, x2, x3);
    }
    if (lane < 16) {
        int c0 = 128 + lane * 4;
        float x0 = a1.x * inv + bias[c0], x1 = a1.y * inv + bias[c0 + 1];
        float x2 = a1.z * inv + bias[c0 + 2], x3 = a1.w * inv + bias[c0 + 3];
        x0 = x0 > 0.f ? x0 : expm1f(x0); x1 = x1 > 0.f ? x1 : expm1f(x1);
        x2 = x2 > 0.f ? x2 : expm1f(x2); x3 = x3 > 0.f ? x3 : expm1f(x3);
        store_split4(out3 + rowb + c0, x0, x1, x2, x3);
    }
}

// warp per graph: segment-sum pool + relu + split
__global__ void k_pool_seg() {
    int g = (blockIdx.x * blockDim.x + threadIdx.x) >> 5;
    int lane = threadIdx.x & 31;
    if (g >= GG) return;
    int p0 = g_molptr[g], p1 = g_molptr[g + 1];
    float4 a0 = make_float4(0.f, 0.f, 0.f, 0.f);
    float4 a1 = make_float4(0.f, 0.f, 0.f, 0.f);
    for (int i = p0; i < p1; i++) {
        const float4* xr = (const float4*)(g_x + (size_t)i * HH);
        float4 v = xr[lane];
        a0.x += v.x; a0.y += v.y; a0.z += v.z; a0.w += v.w;
        if (lane < 16) {
            float4 v2 = xr[lane + 32];
            a1.x += v2.x; a1.y += v2.y; a1.z += v2.z; a1.w += v2.w;
        }
    }
    a0.x = fmaxf(a0.x, 0.f); a0.y = fmaxf(a0.y, 0.f);
    a0.z = fmaxf(a0.z, 0.f); a0.w = fmaxf(a0.w, 0.f);
    size_t rowb = (size_t)g * K2A;
    ((float4*)(g_out + (size_t)g * HH))[lane] = a0;
    store_split4(g_a3m + rowb + lane * 4, a0.x, a0.y, a0.z, a0.w);
    if (lane < 16) {
        a1.x = fmaxf(a1.x, 0.f); a1.y = fmaxf(a1.y, 0.f);
        a1.z = fmaxf(a1.z, 0.f); a1.w = fmaxf(a1.w, 0.f);
        ((float4*)(g_out + (size_t)g * HH))[lane + 32] = a1;
        store_split4(g_a3m + rowb + 128 + lane * 4, a1.x, a1.y, a1.z, a1.w);
    }
}

// warp per graph: mol GAT gather + ELU + bias + split -> a3m2
__global__ void k_molgather(const float* __restrict__ mol_b) {
    int g = (blockIdx.x * blockDim.x + threadIdx.x) >> 5;
    int lane = threadIdx.x & 31;
    if (g >= GG) return;
    int p0 = g_molptr[g], p1 = g_molptr[g + 1];
    float dg = g_dmol[g];
    float se = 0.f;
    for (int i = p0 + lane; i < p1; i += 32) {
        float a = g_smol[i] + dg;
        a = a >= 0.f ? a : 0.01f * a;
        se += expf(a);
    }
    se = warp_sum(se);
    se = __shfl_sync(0xffffffffu, se, 0);
    float inv = 1.f / (se + 1e-16f);
    float4 a0 = make_float4(0.f, 0.f, 0.f, 0.f);
    float4 a1 = make_float4(0.f, 0.f, 0.f, 0.f);
    for (int i = p0; i < p1; i++) {
        float a = g_smol[i] + dg;
        a = a >= 0.f ? a : 0.01f * a;
        float w = expf(a);
        const __half* hs = g_hWh + (size_t)i * HH;
        float f0, f1, f2, f3;
        ldh4(hs + lane * 4, f0, f1, f2, f3);
        a0.x += w * f0; a0.y += w * f1; a0.z += w * f2; a0.w += w * f3;
        if (lane < 16) {
            ldh4(hs + 128 + lane * 4, f0, f1, f2, f3);
            a1.x += w * f0; a1.y += w * f1; a1.z += w * f2; a1.w += w * f3;
        }
    }
    size_t rowb = (size_t)g * K2A;
    {
        int c0 = lane * 4;
        float x0 = a0.x * inv + mol_b[c0], x1 = a0.y * inv + mol_b[c0 + 1];
        float x2 = a0.z * inv + mol_b[c0 + 2], x3 = a0.w * inv + mol_b[c0 + 3];
        x0 = x0 > 0.f ? x0 : expm1f(x0); x1 = x1 > 0.f ? x1 : expm1f(x1);
        x2 = x2 > 0.f ? x2 : expm1f(x2); x3 = x3 > 0.f ? x3 : expm1f(x3);
        store_split4(g_a3m2 + rowb + c0, x0, x1, x2, x3);
    }
    if (lane < 16) {
        int c0 = 128 + lane * 4;
        float x0 = a1.x * inv + mol_b[c0], x1 = a1.y * inv + mol_b[c0 + 1];
        float x2 = a1.z * inv + mol_b[c0 + 2], x3 = a1.w * inv + mol_b[c0 + 3];
        x0 = x0 > 0.f ? x0 : expm1f(x0); x1 = x1 > 0.f ? x1 : expm1f(x1);
        x2 = x2 > 0.f ? x2 : expm1f(x2); x3 = x3 > 0.f ? x3 : expm1f(x3);
        store_split4(g_a3m2 + rowb + c0, x0, x1, x2, x3);
    }
}

__global__ void k_final(const float* __restrict__ W, const float* __restrict__ b,
                        float* __restrict__ out) {
    int gw = (blockIdx.x * blockDim.x + threadIdx.x) >> 5;
    int lane = threadIdx.x & 31;
    if (gw >= GG) return;
    float s = 0.f;
    for (int k = lane; k < HH; k += 32) s += g_out[gw * HH + k] * W[k];
    s = warp_sum(s);
    if (lane == 0) out[gw] = s + b[0];
}

// ---------------- host ----------------
static inline int cdiv(int a, int b) { return (a + b - 1) / b; }

extern "C" void kernel_launch(void* const* d_in, const int* in_sizes, int n_in,
                              void* d_out, int out_size) {
    const float* x_in = (const float*)d_in[0];
    const int* eidx = (const int*)d_in[1];
    const float* eattr = (const float*)d_in[2];
    const int* batch = (const int*)d_in[3];
    const float* lin1_W = (const float*)d_in[4];
    const float* lin1_b = (const float*)d_in[5];
    const float* conv0_W = (const float*)d_in[6];
    const float* conv0_att_s = (const float*)d_in[7];
    const float* conv0_att_d = (const float*)d_in[8];
    const float* conv0_We = (const float*)d_in[9];
    const float* conv0_att_e = (const float*)d_in[10];
    const float* conv0_b = (const float*)d_in[11];
    const float* convs_W = (const float*)d_in[12];
    const float* convs_att_s = (const float*)d_in[13];
    const float* convs_att_d = (const float*)d_in[14];
    const float* convs_b = (const float*)d_in[15];
    const float* gru_Wih = (const float*)d_in[16];
    const float* gru_Whh = (const float*)d_in[17];
    const float* gru_bih = (const float*)d_in[18];
    const float* gru_bhh = (const float*)d_in[19];
    const float* mol_Wsrc = (const float*)d_in[20];
    const float* mol_Wdst = (const float*)d_in[21];
    const float* mol_att_s = (const float*)d_in[22];
    const float* mol_att_d = (const float*)d_in[23];
    const float* mol_b = (const float*)d_in[24];
    const float* mgru_Wih = (const float*)d_in[25];
    const float* mgru_Whh = (const float*)d_in[26];
    const float* mgru_bih = (const float*)d_in[27];
    const float* mgru_bhh = (const float*)d_in[28];
    const float* lin2_W = (const float*)d_in[29];
    const float* lin2_b = (const float*)d_in[30];

    const int* src = eidx;
    const int* dst = eidx + EE;

    float *px, *pgh, *ps, *pd, *pout, *psmol, *pdmol;
    float *bp_ih, *bp_hh, *bp_mi, *bp_mh;
    int* pdeg;
    __half* phWh;
    cudaGetSymbolAddress((void**)&px, g_x);
    cudaGetSymbolAddress((void**)&phWh, g_hWh);
    cudaGetSymbolAddress((void**)&pgh, g_gh);
    cudaGetSymbolAddress((void**)&ps, g_s);
    cudaGetSymbolAddress((void**)&pd, g_d);
    cudaGetSymbolAddress((void**)&pout, g_out);
    cudaGetSymbolAddress((void**)&psmol, g_smol);
    cudaGetSymbolAddress((void**)&pdmol, g_dmol);
    cudaGetSymbolAddress((void**)&pdeg, g_deg);
    cudaGetSymbolAddress((void**)&bp_ih, g_bp_ih);
    cudaGetSymbolAddress((void**)&bp_hh, g_bp_hh);
    cudaGetSymbolAddress((void**)&bp_mi, g_bp_mi);
    cudaGetSymbolAddress((void**)&bp_mh, g_bp_mh);
    __half *a3, *a3b, *b3, *b3wd, *b3wi, *b3wh, *a3m, *a3m2;
    cudaGetSymbolAddress((void**)&a3, g_a3);
    cudaGetSymbolAddress((void**)&a3b, g_a3b);
    cudaGetSymbolAddress((void**)&b3, g_b3);
    cudaGetSymbolAddress((void**)&b3wd, g_b3wd);
    cudaGetSymbolAddress((void**)&b3wi, g_b3wi);
    cudaGetSymbolAddress((void**)&b3wh, g_b3wh);
    cudaGetSymbolAddress((void**)&a3m, g_a3m);
    cudaGetSymbolAddress((void**)&a3m2, g_a3m2);

    cudaFuncSetAttribute(bgemm<1, false, false, false>, cudaFuncAttributeMaxDynamicSharedMemorySize, BG_SMEM);
    cudaFuncSetAttribute(bgemm<2, true, false, false>, cudaFuncAttributeMaxDynamicSharedMemorySize, BG_SMEM);
    cudaFuncSetAttribute(bgemm<0, false, true, false>, cudaFuncAttributeMaxDynamicSharedMemorySize, BG_SMEM);
    cudaFuncSetAttribute(bgemm<0, false, false, true>, cudaFuncAttributeMaxDynamicSharedMemorySize, BG_SMEM);

    cudaStream_t s2;
    cudaStreamCreate(&s2);
    cudaEvent_t ev[32];
    for (int i = 0; i < 32; i++) cudaEventCreateWithFlags(&ev[i], cudaEventDisableTiming);
#define REC0(i) cudaEventRecord(ev[i], 0)
#define RECS(i) cudaEventRecord(ev[i], s2)
#define W0(i) cudaStreamWaitEvent(0, ev[i], 0)
#define WS(i) cudaStreamWaitEvent(s2, ev[i], 0)

    auto bg1 = [&](const __half* A, const __half* B, const float* bias,
                   float* C, int M, int Nc, int K3, cudaStream_t st) {
        bgemm<1, false, false, false><<<dim3(Nc / BN, cdiv(M, 128)), 256, BG_SMEM, st>>>(
            A, B, bias, C, nullptr, nullptr, nullptr, nullptr, nullptr, nullptr, nullptr, M, Nc, K3);
    };
    // DOT GEMM: writes fp16 hW (Ch) + fused rowdots
    auto bgD = [&](const __half* A, const __half* B, __half* Ch,
                   const float* u, const float* w, float* ou, float* ow,
                   int M, int Nc, int K3) {
        bgemm<0, false, true, false><<<dim3(Nc / BN, cdiv(M, 128)), 256, BG_SMEM>>>(
            A, B, nullptr, nullptr, Ch, u, w, ou, ow, nullptr, nullptr, M, Nc, K3);
    };
    auto bgGRU = [&](const __half* A, const __half* B, const float* bias_p,
                     const float* ghp, float* xb, __half* out3, int M) {
        bgemm<0, false, false, true><<<dim3(H3 / BN, cdiv(M, 128)), 256, BG_SMEM>>>(
            A, B, bias_p, nullptr, out3, nullptr, nullptr, nullptr, nullptr, ghp, xb, M, H3, K2A);
    };

    // ---- main prologue (slot 3 = bgD profiled) ----
    REC0(0);
    k_splitA<<<cdiv(NN * CC, 256), 256>>>(x_in, a3b);
    k_splitB2<<<cdiv(HH * CC + HH * HH, 256), 256>>>(lin1_W, b3wd, conv0_W, b3);
    bgemm<2, true, false, false><<<dim3(HH / BN, cdiv(NN, 128)), 256, BG_SMEM>>>(
        a3b, b3wd, lin1_b, px, a3, nullptr, nullptr, nullptr, nullptr, nullptr, nullptr,
        NN, HH, 2 * CC);
    REC0(1);  // a3 ready
    bgD(a3, b3, phWh, conv0_att_s, conv0_att_d, ps, pd, NN, HH, K2A);  // PROFILED

    // ---- s2: ae + CSR + conv0 gh chain ----
    WS(0);
    k_v2<<<1, 512, 0, s2>>>(conv0_We, conv0_att_e);
    k_ae<<<cdiv(EE, 256), 256, 0, s2>>>(eattr);
    RECS(2);
    k_zero_int<<<cdiv(NN, 256), 256, 0, s2>>>(pdeg, NN);
    k_hist<<<cdiv(EE, 256), 256, 0, s2>>>(dst);
    k_scan_block<<<NSCAN, SCAN_BLK, 0, s2>>>();
    k_scan_mid<<<1, 32, 0, s2>>>();
    k_scan_add<<<cdiv(NN + 1, 256), 256, 0, s2>>>();
    k_fill<<<cdiv(EE, 256), 256, 0, s2>>>(dst, src);
    k_molptr<<<cdiv(GG + 1, 256), 256, 0, s2>>>(batch);
    RECS(3);
    WS(1);
    k_splitB_perm<<<cdiv(H3 * HH, 256), 256, 0, s2>>>(gru_Whh, b3wh);
    k_permbias<<<1, H3, 0, s2>>>(gru_bhh, bp_hh, gru_bih, bp_ih);
    bg1(a3, b3wh, bp_hh, pgh, NN, H3, K2A, s2);
    RECS(4);

    // ---- conv0 main chain ----
    W0(2);
    k_edge_alpha<true><<<cdiv(EE, 256), 256>>>(src, dst);
    W0(3);
    k_splitB_perm<<<cdiv(H3 * HH, 256), 256>>>(gru_Wih, b3wi);
    k_gather<true><<<cdiv(NN * 32, 256), 256>>>(conv0_b, a3b);
    W0(4);
    bgGRU(a3b, b3wi, bp_ih, pgh, px, a3, NN);
    REC0(5);

    // ---- remaining atom conv layers ----
    for (int l = 0; l < 2; l++) {
        WS(5 + 2 * l);
        k_splitB_perm<<<cdiv(H3 * HH, 256), 256, 0, s2>>>(gru_Whh + (size_t)(l + 1) * H3 * HH, b3wh);
        k_permbias<<<1, H3, 0, s2>>>(gru_bhh + (l + 1) * H3, bp_hh, gru_bih + (l + 1) * H3, bp_ih);
        bg1(a3, b3wh, bp_hh, pgh, NN, H3, K2A, s2);
        RECS(6 + 2 * l);
        k_splitB<<<cdiv(HH * HH, 256), 256>>>(convs_W + (size_t)l * HH * HH, b3, HH, HH);
        k_zero2<<<cdiv(NN, 256), 256>>>(ps, pd, NN, NN);
        bgD(a3, b3, phWh, convs_att_s + l * HH, convs_att_d + l * HH, ps, pd, NN, HH, K2A);
        k_edge_alpha<false><<<cdiv(EE, 256), 256>>>(src, dst);
        k_splitB_perm<<<cdiv(H3 * HH, 256), 256>>>(gru_Wih + (size_t)(l + 1) * H3 * HH, b3wi);
        k_gather<false><<<cdiv(NN * 32, 256), 256>>>(convs_b + l * HH, a3b);
        W0(6 + 2 * l);
        bgGRU(a3b, b3wi, bp_ih, pgh, px, a3, NN);
        REC0(7 + 2 * l);  // 7, 9
    }

    // ---- molecule readout ----
    WS(9);
    k_pool_seg<<<cdiv(GG * 32, 256), 256, 0, s2>>>();
    k_splitB<<<cdiv(HH * HH, 256), 256, 0, s2>>>(mol_Wdst, b3wd, HH, HH);
    k_splitB_perm<<<cdiv(H3 * HH, 256), 256, 0, s2>>>(mgru_Wih, b3wi);
    k_splitB_perm<<<cdiv(H3 * HH, 256), 256, 0, s2>>>(mgru_Whh, b3wh);
    k_permbias<<<1, H3, 0, s2>>>(mgru_bih, bp_mi, mgru_bhh, bp_mh);
    RECS(10);
    k_splitB<<<cdiv(HH * HH, 256), 256>>>(mol_Wsrc, b3, HH, HH);
    k_zero2<<<cdiv(NN, 256), 256>>>(psmol, psmol, NN, 0);
    bgD(a3, b3, phWh, mol_att_s, nullptr, psmol, nullptr, NN, HH, K2A);
    W0(10);

    for (int t = 0; t < 2; t++) {
        REC0(11 + 2 * t);
        WS(11 + 2 * t);
        bg1(a3m, b3wh, bp_mh, pgh, GG, H3, K2A, s2);
        RECS(12 + 2 * t);
        k_zero2<<<cdiv(GG, 256), 256>>>(pdmol, pdmol, GG, 0);
        bgD(a3m, b3wd, nullptr, mol_att_d, nullptr, pdmol, nullptr, GG, HH, K2A);
        k_molgather<<<cdiv(GG * 32, 256), 256>>>(mol_b);
        W0(12 + 2 * t);
        bgGRU(a3m2, b3wi, bp_mi, pgh, pout, a3m, GG);
    }

    k_final<<<cdiv(GG * 32, 256), 256>>>(lin2_W, lin2_b, (float*)d_out);
#undef REC0
#undef RECS
#undef W0
#undef WS
}